// round 2
// baseline (speedup 1.0000x reference)
#include <cuda_runtime.h>
#include <math.h>

// ---------------------------------------------------------------------------
// Problem constants
// ---------------------------------------------------------------------------
#define BATCH 8
#define NH 8
#define SEQ 512
#define DIM 512
#define HD 64
#define NBLOCKS 18

// ---------------------------------------------------------------------------
// Scratch (device globals; no allocations allowed)
// ---------------------------------------------------------------------------
__device__ float g_U0[BATCH * SEQ * DIM];   // unified l
__device__ float g_U1[BATCH * SEQ * DIM];   // unified v
__device__ float g_U2[BATCH * SEQ * DIM];   // unified a
__device__ float g_q0[BATCH * SEQ * DIM];
__device__ float g_q1[BATCH * SEQ * DIM];
__device__ float g_ctx[BATCH * SEQ * DIM];
__device__ float g_x[BATCH * SEQ * DIM];
__device__ float g_tmp[BATCH * SEQ * DIM];
__device__ float g_S[BATCH * NH * SEQ * SEQ];   // layer-0 scores (post-mask)
__device__ float g_P[BATCH * NH * SEQ * SEQ];   // probs / layer-1 scores
__device__ float g_sum[6 * BATCH * DIM];
__device__ float g_max[6 * BATCH * DIM];

// ---------------------------------------------------------------------------
// Generic NN SGEMM: C[M,N] = A[M,K] @ B[K,N], row-major.
// Optional split-A (concat along K): for k >= Ksplit read A2[row, k-Ksplit].
// Batched over blockIdx.z with composite (b,h) strides, z = b*H + h.
// 64x64 tile, BK=16, 256 threads, 4x4 per thread.
// ---------------------------------------------------------------------------
__global__ void __launch_bounds__(256) sgemm_nn(
    const float* __restrict__ A, const float* __restrict__ A2, int Ksplit,
    const float* __restrict__ Bm, float* __restrict__ C,
    int M, int N, int K, int lda, int ldb, int ldc,
    int H, long sAb, long sAh, long sBb, long sBh, long sCb, long sCh)
{
    int z = blockIdx.z;
    int bb = z / H, hh = z % H;
    A += (long)bb * sAb + (long)hh * sAh;
    if (A2) A2 += (long)bb * sAb + (long)hh * sAh;
    Bm += (long)bb * sBb + (long)hh * sBh;
    C += (long)bb * sCb + (long)hh * sCh;

    __shared__ float As[16][64];
    __shared__ float Bs[16][64];

    int tid = threadIdx.x;
    int bm = blockIdx.y * 64;
    int bn = blockIdx.x * 64;
    int tr = (tid / 16) * 4;
    int tc = (tid % 16) * 4;

    int arow = tid / 4;
    int acol = (tid % 4) * 4;
    int brow = tid / 16;
    int bcol = (tid % 16) * 4;

    float acc[4][4] = {};

    for (int k0 = 0; k0 < K; k0 += 16) {
#pragma unroll
        for (int i = 0; i < 4; i++) {
            int kk = k0 + acol + i;
            float v = 0.f;
            if (kk < K) {
                if (A2 && kk >= Ksplit)
                    v = A2[(long)(bm + arow) * lda + (kk - Ksplit)];
                else
                    v = A[(long)(bm + arow) * lda + kk];
            }
            As[acol + i][arow] = v;
        }
#pragma unroll
        for (int i = 0; i < 4; i++) {
            int kk = k0 + brow;
            float v = 0.f;
            if (kk < K) v = Bm[(long)kk * ldb + bn + bcol + i];
            Bs[brow][bcol + i] = v;
        }
        __syncthreads();
#pragma unroll
        for (int kk = 0; kk < 16; kk++) {
            float ra[4], rb[4];
#pragma unroll
            for (int i = 0; i < 4; i++) ra[i] = As[kk][tr + i];
#pragma unroll
            for (int j = 0; j < 4; j++) rb[j] = Bs[kk][tc + j];
#pragma unroll
            for (int i = 0; i < 4; i++)
#pragma unroll
                for (int j = 0; j < 4; j++)
                    acc[i][j] += ra[i] * rb[j];
        }
        __syncthreads();
    }

#pragma unroll
    for (int i = 0; i < 4; i++)
#pragma unroll
        for (int j = 0; j < 4; j++)
            C[(long)(bm + tr + i) * ldc + bn + tc + j] = acc[i][j];
}

// ---------------------------------------------------------------------------
// Scores GEMM (NT): S[b,h,q,k] = (Q[b,q,h,:] . K[b,k,h,:]) * 0.125
//                   (+ c[idx] * prev)  (- 1e8*(1-mask[b,k]))
// Q,K layout [B,SEQ,DIM] row-major; head hh slice at column hh*64.
// ---------------------------------------------------------------------------
__global__ void __launch_bounds__(256) sgemm_nt_scores(
    const float* __restrict__ Q, const float* __restrict__ Kv,
    float* __restrict__ S, const float* __restrict__ prev,
    const float* __restrict__ mask, const float* __restrict__ cptr, int cidx)
{
    int z = blockIdx.z;
    int bb = z >> 3, hh = z & 7;
    const float* Qp = Q + (long)bb * (SEQ * DIM) + hh * HD;
    const float* Kp = Kv + (long)bb * (SEQ * DIM) + hh * HD;
    long coff = (long)z * (SEQ * SEQ);
    float* Sp = S + coff;
    const float* Pp = prev ? prev + coff : nullptr;
    const float* mp = mask + bb * SEQ;

    __shared__ float Qs[64][65];
    __shared__ float Ks[64][65];

    int tid = threadIdx.x;
    int bm = blockIdx.y * 64;   // q tile
    int bn = blockIdx.x * 64;   // k tile
    int tr = (tid / 16) * 4;
    int tc = (tid % 16) * 4;

#pragma unroll
    for (int i = 0; i < 16; i++) {
        int idx = tid + i * 256;
        int row = idx >> 6, col = idx & 63;
        Qs[row][col] = Qp[(long)(bm + row) * DIM + col];
        Ks[row][col] = Kp[(long)(bn + row) * DIM + col];
    }
    __syncthreads();

    float acc[4][4] = {};
#pragma unroll 8
    for (int kk = 0; kk < 64; kk++) {
        float ra[4], rb[4];
#pragma unroll
        for (int i = 0; i < 4; i++) ra[i] = Qs[tr + i][kk];
#pragma unroll
        for (int j = 0; j < 4; j++) rb[j] = Ks[tc + j][kk];
#pragma unroll
        for (int i = 0; i < 4; i++)
#pragma unroll
            for (int j = 0; j < 4; j++)
                acc[i][j] += ra[i] * rb[j];
    }

    float cv = 0.f;
    if (Pp) cv = cptr[cidx];

#pragma unroll
    for (int i = 0; i < 4; i++) {
        int r = bm + tr + i;
#pragma unroll
        for (int j = 0; j < 4; j++) {
            int col = bn + tc + j;
            float v = acc[i][j] * 0.125f;
            if (Pp) v += cv * Pp[(long)r * SEQ + col];
            v -= 1e8f * (1.f - mp[col]);
            Sp[(long)r * SEQ + col] = v;
        }
    }
}

// ---------------------------------------------------------------------------
// Row softmax over 512 (one block per row). src may equal dst.
// ---------------------------------------------------------------------------
__global__ void __launch_bounds__(256) softmax_kernel(
    const float* __restrict__ src, float* __restrict__ dst)
{
    long row = blockIdx.x;
    const float* p = src + row * SEQ;
    float* q = dst + row * SEQ;
    int tid = threadIdx.x;
    float v0 = p[tid], v1 = p[tid + 256];

    __shared__ float red[256];
    red[tid] = fmaxf(v0, v1);
    __syncthreads();
    for (int s = 128; s > 0; s >>= 1) {
        if (tid < s) red[tid] = fmaxf(red[tid], red[tid + s]);
        __syncthreads();
    }
    float m = red[0];
    __syncthreads();

    float e0 = expf(v0 - m), e1 = expf(v1 - m);
    red[tid] = e0 + e1;
    __syncthreads();
    for (int s = 128; s > 0; s >>= 1) {
        if (tid < s) red[tid] += red[tid + s];
        __syncthreads();
    }
    float inv = 1.f / red[0];
    q[tid] = e0 * inv;
    q[tid + 256] = e1 * inv;
}

// ---------------------------------------------------------------------------
// LayerNorm over last dim 512 (one block per row).
// ---------------------------------------------------------------------------
__global__ void __launch_bounds__(256) ln_kernel(
    const float* __restrict__ X, float* __restrict__ Y,
    const float* __restrict__ g, const float* __restrict__ b)
{
    long row = blockIdx.x;
    const float* x = X + row * DIM;
    float* y = Y + row * DIM;
    int tid = threadIdx.x;
    float v0 = x[tid], v1 = x[tid + 256];

    __shared__ float red[256];
    red[tid] = v0 + v1;
    __syncthreads();
    for (int s = 128; s > 0; s >>= 1) {
        if (tid < s) red[tid] += red[tid + s];
        __syncthreads();
    }
    float mu = red[0] * (1.f / DIM);
    __syncthreads();

    float d0 = v0 - mu, d1 = v1 - mu;
    red[tid] = d0 * d0 + d1 * d1;
    __syncthreads();
    for (int s = 128; s > 0; s >>= 1) {
        if (tid < s) red[tid] += red[tid + s];
        __syncthreads();
    }
    float rstd = rsqrtf(red[0] * (1.f / DIM) + 1e-5f);

    y[tid] = d0 * rstd * g[tid] + b[tid];
    y[tid + 256] = d1 * rstd * g[tid + 256] + b[tid + 256];
}

// ---------------------------------------------------------------------------
// Pooling
// ---------------------------------------------------------------------------
__global__ void pool_init(float* s, float* m, int n)
{
    int i = blockIdx.x * blockDim.x + threadIdx.x;
    if (i < n) { s[i] = 0.f; m[i] = -INFINITY; }
}

__global__ void __launch_bounds__(256) pool_reduce(
    const float* __restrict__ O, float* __restrict__ sum, float* __restrict__ mx)
{
    int idx = blockIdx.x * 256 + threadIdx.x;   // 0..4095 -> (b, d)
    int bb = idx >> 9, d = idx & 511;
    const float* p = O + (long)bb * (SEQ * DIM) + d;
    float s = 0.f, m = -INFINITY;
#pragma unroll 4
    for (int r = 0; r < SEQ; r++) {
        float v = p[(long)r * DIM];
        s += v;
        m = fmaxf(m, v);
    }
    sum[idx] += s;
    mx[idx] = fmaxf(mx[idx], m);
}

// ---------------------------------------------------------------------------
// Classifier: out[b,c] = sum_j mean[b,j]*W[j,c] + max[b,j]*W[3072+j,c]
// ---------------------------------------------------------------------------
__global__ void __launch_bounds__(256) clf_kernel(
    const float* __restrict__ sum, const float* __restrict__ mx,
    const float* __restrict__ W, float* __restrict__ out)
{
    int bb = blockIdx.x / 9, cls = blockIdx.x % 9;
    int tid = threadIdx.x;
    float acc = 0.f;
    for (int j = tid; j < 3072; j += 256) {
        int k = j >> 9, d = j & 511;
        float sm = sum[k * 4096 + bb * 512 + d] * (1.f / 1536.f);
        float mv = mx[k * 4096 + bb * 512 + d];
        acc += sm * W[(long)j * 9 + cls] + mv * W[(long)(3072 + j) * 9 + cls];
    }
    __shared__ float red[256];
    red[tid] = acc;
    __syncthreads();
    for (int s = 128; s > 0; s >>= 1) {
        if (tid < s) red[tid] += red[tid + s];
        __syncthreads();
    }
    if (tid == 0) out[bb * 9 + cls] = red[0];
}

// ---------------------------------------------------------------------------
// Host orchestration
// ---------------------------------------------------------------------------
extern "C" void kernel_launch(void* const* d_in, const int* in_sizes, int n_in,
                              void* d_out, int out_size)
{
    const float* l      = (const float*)d_in[0];
    const float* v      = (const float*)d_in[1];
    const float* a      = (const float*)d_in[2];
    const float* l_mask = (const float*)d_in[3];
    const float* v_mask = (const float*)d_in[4];
    const float* a_mask = (const float*)d_in[5];
    const float* wl     = (const float*)d_in[6];
    const float* wv     = (const float*)d_in[7];
    const float* wa     = (const float*)d_in[8];
    const float* n1_g   = (const float*)d_in[9];
    const float* n1_b   = (const float*)d_in[10];
    const float* proj_w = (const float*)d_in[11];
    const float* minus_w= (const float*)d_in[12];
    const float* n2_g   = (const float*)d_in[13];
    const float* n2_b   = (const float*)d_in[14];
    const float* cvec   = (const float*)d_in[15];
    const float* clf_w  = (const float*)d_in[16];
    float* out          = (float*)d_out;

    float *pU0, *pU1, *pU2, *pq0, *pq1, *pctx, *px, *ptmp, *pS, *pP, *psum, *pmax;
    cudaGetSymbolAddress((void**)&pU0, g_U0);
    cudaGetSymbolAddress((void**)&pU1, g_U1);
    cudaGetSymbolAddress((void**)&pU2, g_U2);
    cudaGetSymbolAddress((void**)&pq0, g_q0);
    cudaGetSymbolAddress((void**)&pq1, g_q1);
    cudaGetSymbolAddress((void**)&pctx, g_ctx);
    cudaGetSymbolAddress((void**)&px, g_x);
    cudaGetSymbolAddress((void**)&ptmp, g_tmp);
    cudaGetSymbolAddress((void**)&pS, g_S);
    cudaGetSymbolAddress((void**)&pP, g_P);
    cudaGetSymbolAddress((void**)&psum, g_sum);
    cudaGetSymbolAddress((void**)&pmax, g_max);

    const int M = BATCH * SEQ;   // 4096

    // pool init
    pool_init<<<96, 256>>>(psum, pmax, 6 * BATCH * DIM);

    // --- Unify + LN ---
    const float* uin[3] = { l, v, a };
    const float* uw[3]  = { wl, wv, wa };
    const int    uk[3]  = { 768, 640, 205 };
    float* U[3] = { pU0, pU1, pU2 };
    for (int m = 0; m < 3; m++) {
        sgemm_nn<<<dim3(DIM / 64, M / 64, 1), 256>>>(
            uin[m], nullptr, 0, uw[m], ptmp,
            M, DIM, uk[m], uk[m], DIM, DIM,
            1, 0, 0, 0, 0, 0, 0);
        ln_kernel<<<M, 256>>>(ptmp, U[m], n1_g, n1_b);
    }

    // --- 9 streams x 2 layers ---
    const int qsrc[9] = { 0, 0, 0, 1, 1, 1, 2, 2, 2 };
    const int kvi[9]  = { 0, 1, 2, 1, 0, 2, 2, 0, 1 };
    const float* masks[3] = { l_mask, v_mask, a_mask };

    for (int off = 0; off < 9; off++) {
        const float* kv  = U[kvi[off]];
        const float* msk = masks[kvi[off]];
        const float* qin = U[qsrc[off]];
        float* qouts[2] = { pq0, pq1 };

        for (int j = 0; j < 2; j++) {
            int i = off * 2 + j;
            float* Sout = (j == 0) ? pS : pP;
            const float* prev = (j == 0) ? nullptr : pS;

            // scores (+ residual + mask)
            sgemm_nt_scores<<<dim3(8, 8, BATCH * NH), 256>>>(
                qin, kv, Sout, prev, msk, cvec, i);

            // softmax: layer0 S->P (keep S), layer1 in-place on P
            softmax_kernel<<<BATCH * NH * SEQ, 256>>>(Sout, pP);

            // ctx[b,q,h*64+d] = P[b,h] @ kv_head
            sgemm_nn<<<dim3(1, SEQ / 64, BATCH * NH), 256>>>(
                pP, nullptr, 0, kv, pctx,
                SEQ, HD, SEQ, SEQ, DIM, DIM,
                NH,
                (long)NH * SEQ * SEQ, (long)SEQ * SEQ,
                (long)SEQ * DIM, HD,
                (long)SEQ * DIM, HD);

            // x = ctx @ proj_w[i]
            sgemm_nn<<<dim3(DIM / 64, M / 64, 1), 256>>>(
                pctx, nullptr, 0, proj_w + (long)i * DIM * DIM, px,
                M, DIM, DIM, DIM, DIM, DIM,
                1, 0, 0, 0, 0, 0, 0);

            // tmp = [qin, x] @ minus_w[i]
            sgemm_nn<<<dim3(DIM / 64, M / 64, 1), 256>>>(
                qin, px, DIM, minus_w + (long)i * 2 * DIM * DIM, ptmp,
                M, DIM, 2 * DIM, DIM, DIM, DIM,
                1, 0, 0, 0, 0, 0, 0);

            // LN -> new q
            float* qout = qouts[j];
            ln_kernel<<<M, 256>>>(ptmp, qout, n2_g + (long)i * DIM, n2_b + (long)i * DIM);

            // pool into slot k
            int k = (off % 3) * 2 + j;
            pool_reduce<<<16, 256>>>(qout, psum + (long)k * 4096, pmax + (long)k * 4096);

            qin = qout;
        }
    }

    // --- classifier ---
    clf_kernel<<<BATCH * 9, 256>>>(psum, pmax, clf_w, out);
}

// round 3
// speedup vs baseline: 1.6071x; 1.6071x over previous
#include <cuda_runtime.h>
#include <math.h>

// ---------------------------------------------------------------------------
// Problem constants
// ---------------------------------------------------------------------------
#define BATCH 8
#define NH 8
#define SEQ 512
#define DIM 512
#define HD 64
#define NBLOCKS 18

// ---------------------------------------------------------------------------
// Scratch (device globals; no allocations allowed)
// ---------------------------------------------------------------------------
__device__ float g_U0[BATCH * SEQ * DIM];   // unified l
__device__ float g_U1[BATCH * SEQ * DIM];   // unified v
__device__ float g_U2[BATCH * SEQ * DIM];   // unified a
__device__ float g_q0[BATCH * SEQ * DIM];
__device__ float g_q1[BATCH * SEQ * DIM];
__device__ float g_ctx[BATCH * SEQ * DIM];
__device__ float g_x[BATCH * SEQ * DIM];
__device__ float g_tmp[BATCH * SEQ * DIM];
__device__ float g_S[BATCH * NH * SEQ * SEQ];   // layer-0 scores (post-mask)
__device__ float g_P[BATCH * NH * SEQ * SEQ];   // probs / layer-1 scores
__device__ float g_sum[6 * BATCH * DIM];
__device__ float g_max[6 * BATCH * DIM];

// ---------------------------------------------------------------------------
// Generic NN SGEMM: C[M,N] = A[M,K] @ B[K,N], row-major.
// Optional split-A (concat along K): for k >= Ksplit read A2[row, k-Ksplit].
// Batched over blockIdx.z with composite (b,h) strides, z = b*H + h.
// 64x64 tile, BK=16, 256 threads, 4x4 per thread.
// ---------------------------------------------------------------------------
__global__ void __launch_bounds__(256) sgemm_nn(
    const float* __restrict__ A, const float* __restrict__ A2, int Ksplit,
    const float* __restrict__ Bm, float* __restrict__ C,
    int M, int N, int K, int lda, int ldb, int ldc,
    int H, long sAb, long sAh, long sBb, long sBh, long sCb, long sCh)
{
    int z = blockIdx.z;
    int bb = z / H, hh = z % H;
    A += (long)bb * sAb + (long)hh * sAh;
    if (A2) A2 += (long)bb * sAb + (long)hh * sAh;
    Bm += (long)bb * sBb + (long)hh * sBh;
    C += (long)bb * sCb + (long)hh * sCh;

    __shared__ float As[16][64];
    __shared__ float Bs[16][64];

    int tid = threadIdx.x;
    int bm = blockIdx.y * 64;
    int bn = blockIdx.x * 64;
    int tr = (tid / 16) * 4;
    int tc = (tid % 16) * 4;

    int arow = tid / 4;
    int acol = (tid % 4) * 4;
    int brow = tid / 16;
    int bcol = (tid % 16) * 4;

    float acc[4][4] = {};

    for (int k0 = 0; k0 < K; k0 += 16) {
#pragma unroll
        for (int i = 0; i < 4; i++) {
            int kk = k0 + acol + i;
            float v = 0.f;
            if (kk < K) {
                if (A2 && kk >= Ksplit)
                    v = A2[(long)(bm + arow) * lda + (kk - Ksplit)];
                else
                    v = A[(long)(bm + arow) * lda + kk];
            }
            As[acol + i][arow] = v;
        }
#pragma unroll
        for (int i = 0; i < 4; i++) {
            int kk = k0 + brow;
            float v = 0.f;
            if (kk < K) v = Bm[(long)kk * ldb + bn + bcol + i];
            Bs[brow][bcol + i] = v;
        }
        __syncthreads();
#pragma unroll
        for (int kk = 0; kk < 16; kk++) {
            float ra[4], rb[4];
#pragma unroll
            for (int i = 0; i < 4; i++) ra[i] = As[kk][tr + i];
#pragma unroll
            for (int j = 0; j < 4; j++) rb[j] = Bs[kk][tc + j];
#pragma unroll
            for (int i = 0; i < 4; i++)
#pragma unroll
                for (int j = 0; j < 4; j++)
                    acc[i][j] += ra[i] * rb[j];
        }
        __syncthreads();
    }

#pragma unroll
    for (int i = 0; i < 4; i++)
#pragma unroll
        for (int j = 0; j < 4; j++)
            C[(long)(bm + tr + i) * ldc + bn + tc + j] = acc[i][j];
}

// ---------------------------------------------------------------------------
// Scores GEMM (NT): S[b,h,q,k] = (Q[b,q,h,:] . K[b,k,h,:]) * 0.125
//                   (+ c[idx] * prev)  (- 1e8*(1-mask[b,k]))
// Q,K layout [B,SEQ,DIM] row-major; head hh slice at column hh*64.
// ---------------------------------------------------------------------------
__global__ void __launch_bounds__(256) sgemm_nt_scores(
    const float* __restrict__ Q, const float* __restrict__ Kv,
    float* __restrict__ S, const float* __restrict__ prev,
    const float* __restrict__ mask, const float* __restrict__ cptr, int cidx)
{
    int z = blockIdx.z;
    int bb = z >> 3, hh = z & 7;
    const float* Qp = Q + (long)bb * (SEQ * DIM) + hh * HD;
    const float* Kp = Kv + (long)bb * (SEQ * DIM) + hh * HD;
    long coff = (long)z * (SEQ * SEQ);
    float* Sp = S + coff;
    const float* Pp = prev ? prev + coff : nullptr;
    const float* mp = mask + bb * SEQ;

    __shared__ float Qs[64][65];
    __shared__ float Ks[64][65];

    int tid = threadIdx.x;
    int bm = blockIdx.y * 64;   // q tile
    int bn = blockIdx.x * 64;   // k tile
    int tr = (tid / 16) * 4;
    int tc = (tid % 16) * 4;

#pragma unroll
    for (int i = 0; i < 16; i++) {
        int idx = tid + i * 256;
        int row = idx >> 6, col = idx & 63;
        Qs[row][col] = Qp[(long)(bm + row) * DIM + col];
        Ks[row][col] = Kp[(long)(bn + row) * DIM + col];
    }
    __syncthreads();

    float acc[4][4] = {};
#pragma unroll 8
    for (int kk = 0; kk < 64; kk++) {
        float ra[4], rb[4];
#pragma unroll
        for (int i = 0; i < 4; i++) ra[i] = Qs[tr + i][kk];
#pragma unroll
        for (int j = 0; j < 4; j++) rb[j] = Ks[tc + j][kk];
#pragma unroll
        for (int i = 0; i < 4; i++)
#pragma unroll
            for (int j = 0; j < 4; j++)
                acc[i][j] += ra[i] * rb[j];
    }

    float cv = 0.f;
    if (Pp) cv = cptr[cidx];

#pragma unroll
    for (int i = 0; i < 4; i++) {
        int r = bm + tr + i;
#pragma unroll
        for (int j = 0; j < 4; j++) {
            int col = bn + tc + j;
            float v = acc[i][j] * 0.125f;
            if (Pp) v += cv * Pp[(long)r * SEQ + col];
            v -= 1e8f * (1.f - mp[col]);
            Sp[(long)r * SEQ + col] = v;
        }
    }
}

// ---------------------------------------------------------------------------
// Row softmax over 512 (one block per row). src may equal dst.
// ---------------------------------------------------------------------------
__global__ void __launch_bounds__(256) softmax_kernel(
    const float* __restrict__ src, float* __restrict__ dst)
{
    long row = blockIdx.x;
    const float* p = src + row * SEQ;
    float* q = dst + row * SEQ;
    int tid = threadIdx.x;
    float v0 = p[tid], v1 = p[tid + 256];

    __shared__ float red[256];
    red[tid] = fmaxf(v0, v1);
    __syncthreads();
    for (int s = 128; s > 0; s >>= 1) {
        if (tid < s) red[tid] = fmaxf(red[tid], red[tid + s]);
        __syncthreads();
    }
    float m = red[0];
    __syncthreads();

    float e0 = expf(v0 - m), e1 = expf(v1 - m);
    red[tid] = e0 + e1;
    __syncthreads();
    for (int s = 128; s > 0; s >>= 1) {
        if (tid < s) red[tid] += red[tid + s];
        __syncthreads();
    }
    float inv = 1.f / red[0];
    q[tid] = e0 * inv;
    q[tid + 256] = e1 * inv;
}

// ---------------------------------------------------------------------------
// LayerNorm over last dim 512 (one block per row).
// ---------------------------------------------------------------------------
__global__ void __launch_bounds__(256) ln_kernel(
    const float* __restrict__ X, float* __restrict__ Y,
    const float* __restrict__ g, const float* __restrict__ b)
{
    long row = blockIdx.x;
    const float* x = X + row * DIM;
    float* y = Y + row * DIM;
    int tid = threadIdx.x;
    float v0 = x[tid], v1 = x[tid + 256];

    __shared__ float red[256];
    red[tid] = v0 + v1;
    __syncthreads();
    for (int s = 128; s > 0; s >>= 1) {
        if (tid < s) red[tid] += red[tid + s];
        __syncthreads();
    }
    float mu = red[0] * (1.f / DIM);
    __syncthreads();

    float d0 = v0 - mu, d1 = v1 - mu;
    red[tid] = d0 * d0 + d1 * d1;
    __syncthreads();
    for (int s = 128; s > 0; s >>= 1) {
        if (tid < s) red[tid] += red[tid + s];
        __syncthreads();
    }
    float rstd = rsqrtf(red[0] * (1.f / DIM) + 1e-5f);

    y[tid] = d0 * rstd * g[tid] + b[tid];
    y[tid + 256] = d1 * rstd * g[tid + 256] + b[tid + 256];
}

// ---------------------------------------------------------------------------
// Pooling
// ---------------------------------------------------------------------------
__global__ void pool_init(float* s, float* m, int n)
{
    int i = blockIdx.x * blockDim.x + threadIdx.x;
    if (i < n) { s[i] = 0.f; m[i] = -INFINITY; }
}

__global__ void __launch_bounds__(256) pool_reduce(
    const float* __restrict__ O, float* __restrict__ sum, float* __restrict__ mx)
{
    int idx = blockIdx.x * 256 + threadIdx.x;   // 0..4095 -> (b, d)
    int bb = idx >> 9, d = idx & 511;
    const float* p = O + (long)bb * (SEQ * DIM) + d;
    float s = 0.f, m = -INFINITY;
#pragma unroll 4
    for (int r = 0; r < SEQ; r++) {
        float v = p[(long)r * DIM];
        s += v;
        m = fmaxf(m, v);
    }
    sum[idx] += s;
    mx[idx] = fmaxf(mx[idx], m);
}

// ---------------------------------------------------------------------------
// Classifier: out[b,c] = sum_j mean[b,j]*W[j,c] + max[b,j]*W[3072+j,c]
// ---------------------------------------------------------------------------
__global__ void __launch_bounds__(256) clf_kernel(
    const float* __restrict__ sum, const float* __restrict__ mx,
    const float* __restrict__ W, float* __restrict__ out)
{
    int bb = blockIdx.x / 9, cls = blockIdx.x % 9;
    int tid = threadIdx.x;
    float acc = 0.f;
    for (int j = tid; j < 3072; j += 256) {
        int k = j >> 9, d = j & 511;
        float sm = sum[k * 4096 + bb * 512 + d] * (1.f / 1536.f);
        float mv = mx[k * 4096 + bb * 512 + d];
        acc += sm * W[(long)j * 9 + cls] + mv * W[(long)(3072 + j) * 9 + cls];
    }
    __shared__ float red[256];
    red[tid] = acc;
    __syncthreads();
    for (int s = 128; s > 0; s >>= 1) {
        if (tid < s) red[tid] += red[tid + s];
        __syncthreads();
    }
    if (tid == 0) out[bb * 9 + cls] = red[0];
}

// ---------------------------------------------------------------------------
// Host orchestration
// ---------------------------------------------------------------------------
extern "C" void kernel_launch(void* const* d_in, const int* in_sizes, int n_in,
                              void* d_out, int out_size)
{
    const float* l      = (const float*)d_in[0];
    const float* v      = (const float*)d_in[1];
    const float* a      = (const float*)d_in[2];
    const float* l_mask = (const float*)d_in[3];
    const float* v_mask = (const float*)d_in[4];
    const float* a_mask = (const float*)d_in[5];
    const float* wl     = (const float*)d_in[6];
    const float* wv     = (const float*)d_in[7];
    const float* wa     = (const float*)d_in[8];
    const float* n1_g   = (const float*)d_in[9];
    const float* n1_b   = (const float*)d_in[10];
    const float* proj_w = (const float*)d_in[11];
    const float* minus_w= (const float*)d_in[12];
    const float* n2_g   = (const float*)d_in[13];
    const float* n2_b   = (const float*)d_in[14];
    const float* cvec   = (const float*)d_in[15];
    const float* clf_w  = (const float*)d_in[16];
    float* out          = (float*)d_out;

    float *pU0, *pU1, *pU2, *pq0, *pq1, *pctx, *px, *ptmp, *pS, *pP, *psum, *pmax;
    cudaGetSymbolAddress((void**)&pU0, g_U0);
    cudaGetSymbolAddress((void**)&pU1, g_U1);
    cudaGetSymbolAddress((void**)&pU2, g_U2);
    cudaGetSymbolAddress((void**)&pq0, g_q0);
    cudaGetSymbolAddress((void**)&pq1, g_q1);
    cudaGetSymbolAddress((void**)&pctx, g_ctx);
    cudaGetSymbolAddress((void**)&px, g_x);
    cudaGetSymbolAddress((void**)&ptmp, g_tmp);
    cudaGetSymbolAddress((void**)&pS, g_S);
    cudaGetSymbolAddress((void**)&pP, g_P);
    cudaGetSymbolAddress((void**)&psum, g_sum);
    cudaGetSymbolAddress((void**)&pmax, g_max);

    const int M = BATCH * SEQ;   // 4096

    // pool init
    pool_init<<<96, 256>>>(psum, pmax, 6 * BATCH * DIM);

    // --- Unify + LN ---
    const float* uin[3] = { l, v, a };
    const float* uw[3]  = { wl, wv, wa };
    const int    uk[3]  = { 768, 640, 205 };
    float* U[3] = { pU0, pU1, pU2 };
    for (int m = 0; m < 3; m++) {
        sgemm_nn<<<dim3(DIM / 64, M / 64, 1), 256>>>(
            uin[m], nullptr, 0, uw[m], ptmp,
            M, DIM, uk[m], uk[m], DIM, DIM,
            1, 0, 0, 0, 0, 0, 0);
        ln_kernel<<<M, 256>>>(ptmp, U[m], n1_g, n1_b);
    }

    // --- 9 streams x 2 layers ---
    const int qsrc[9] = { 0, 0, 0, 1, 1, 1, 2, 2, 2 };
    const int kvi[9]  = { 0, 1, 2, 1, 0, 2, 2, 0, 1 };
    const float* masks[3] = { l_mask, v_mask, a_mask };

    for (int off = 0; off < 9; off++) {
        const float* kv  = U[kvi[off]];
        const float* msk = masks[kvi[off]];
        const float* qin = U[qsrc[off]];
        float* qouts[2] = { pq0, pq1 };

        for (int j = 0; j < 2; j++) {
            int i = off * 2 + j;
            float* Sout = (j == 0) ? pS : pP;
            const float* prev = (j == 0) ? nullptr : pS;

            // scores (+ residual + mask)
            sgemm_nt_scores<<<dim3(8, 8, BATCH * NH), 256>>>(
                qin, kv, Sout, prev, msk, cvec, i);

            // softmax: layer0 S->P (keep S), layer1 in-place on P
            softmax_kernel<<<BATCH * NH * SEQ, 256>>>(Sout, pP);

            // ctx[b,q,h*64+d] = P[b,h] @ kv_head
            sgemm_nn<<<dim3(1, SEQ / 64, BATCH * NH), 256>>>(
                pP, nullptr, 0, kv, pctx,
                SEQ, HD, SEQ, SEQ, DIM, DIM,
                NH,
                (long)NH * SEQ * SEQ, (long)SEQ * SEQ,
                (long)SEQ * DIM, HD,
                (long)SEQ * DIM, HD);

            // x = ctx @ proj_w[i]
            sgemm_nn<<<dim3(DIM / 64, M / 64, 1), 256>>>(
                pctx, nullptr, 0, proj_w + (long)i * DIM * DIM, px,
                M, DIM, DIM, DIM, DIM, DIM,
                1, 0, 0, 0, 0, 0, 0);

            // tmp = [qin, x] @ minus_w[i]
            sgemm_nn<<<dim3(DIM / 64, M / 64, 1), 256>>>(
                qin, px, DIM, minus_w + (long)i * 2 * DIM * DIM, ptmp,
                M, DIM, 2 * DIM, DIM, DIM, DIM,
                1, 0, 0, 0, 0, 0, 0);

            // LN -> new q
            float* qout = qouts[j];
            ln_kernel<<<M, 256>>>(ptmp, qout, n2_g + (long)i * DIM, n2_b + (long)i * DIM);

            // pool into slot k
            int k = (off % 3) * 2 + j;
            pool_reduce<<<16, 256>>>(qout, psum + (long)k * 4096, pmax + (long)k * 4096);

            qin = qout;
        }
    }

    // --- classifier ---
    clf_kernel<<<BATCH * 9, 256>>>(psum, pmax, clf_w, out);
}

// round 4
// speedup vs baseline: 2.2649x; 1.4093x over previous
#include <cuda_runtime.h>
#include <math.h>

// ---------------------------------------------------------------------------
// Problem constants
// ---------------------------------------------------------------------------
#define BATCH 8
#define NH 8
#define SEQ 512
#define DIM 512
#define HD 64

// ---------------------------------------------------------------------------
// Scratch (device globals; no allocations allowed)
// ---------------------------------------------------------------------------
__device__ float g_U0[BATCH * SEQ * DIM];
__device__ float g_U1[BATCH * SEQ * DIM];
__device__ float g_U2[BATCH * SEQ * DIM];
__device__ float g_q0[BATCH * SEQ * DIM];
__device__ float g_q1[BATCH * SEQ * DIM];
__device__ float g_ctx[BATCH * SEQ * DIM];
__device__ float g_x[BATCH * SEQ * DIM];
__device__ float g_tmp[BATCH * SEQ * DIM];
__device__ float g_S[BATCH * NH * SEQ * SEQ];   // layer-0 scores (post-mask)
__device__ float g_P[BATCH * NH * SEQ * SEQ];   // probs / layer-1 scores
__device__ float g_sum[6 * BATCH * DIM];
__device__ float g_max[6 * BATCH * DIM];

// ---------------------------------------------------------------------------
// TF32 helpers
// ---------------------------------------------------------------------------
__device__ __forceinline__ float to_tf32(float x)
{
    unsigned u;
    asm("cvt.rna.tf32.f32 %0, %1;" : "=r"(u) : "f"(x));
    return __uint_as_float(u);
}

#define MMA_TF32(d, a, b)                                                     \
    asm volatile(                                                             \
        "mma.sync.aligned.m16n8k8.row.col.f32.tf32.tf32.f32 "                 \
        "{%0,%1,%2,%3},{%4,%5,%6,%7},{%8,%9},{%0,%1,%2,%3};"                  \
        : "+f"(d[0]), "+f"(d[1]), "+f"(d[2]), "+f"(d[3])                      \
        : "r"(a[0]), "r"(a[1]), "r"(a[2]), "r"(a[3]), "r"(b[0]), "r"(b[1]))

// ---------------------------------------------------------------------------
// Unified TF32 tensor-core GEMM.
//   C[M,N] = op(A) @ op(B)
//   A row-major [M,K] (optional concat split: k >= Ksplit reads A2)
//   B: transB=0 -> row-major [K,N];  transB=1 -> row-major [N,K] (C = A @ B^T)
//   Batched over blockIdx.z, z = bb*H + hh, with per-operand (b,h) strides.
//   epi: 0 = plain store
//        1 = scores layer0:  v = acc*0.125 - 1e8*(1-mask[col])
//        2 = scores layer1:  v = acc*0.125 + cvec[cidx]*prev - 1e8*(1-mask[col])
// Tile: 128(M) x 64(N) x 16(K); 256 threads = 8 warps (4 along M, 2 along N),
// warp tile 32x32 = 2x4 mma(m16n8k8) tiles. Double-buffered SMEM.
// Requires: M % 128 == 0, N % 64 == 0 (true for all call sites).
// ---------------------------------------------------------------------------
__global__ void __launch_bounds__(256) mma_gemm(
    const float* __restrict__ A, const float* __restrict__ A2, int Ksplit,
    const float* __restrict__ B, int transB, float* __restrict__ C,
    int M, int N, int K, int lda, int ldb, int ldc,
    int H, long sAb, long sAh, long sBb, long sBh, long sCb, long sCh,
    int epi, const float* __restrict__ prev, const float* __restrict__ mask,
    const float* __restrict__ cvec, int cidx)
{
    int z = blockIdx.z;
    int bb = z / H;
    int hh = z - bb * H;
    A += (long)bb * sAb + (long)hh * sAh;
    if (A2) A2 += (long)bb * sAb + (long)hh * sAh;
    B += (long)bb * sBb + (long)hh * sBh;
    C += (long)bb * sCb + (long)hh * sCh;

    __shared__ float As[2][16][136];   // [k][m], stride 136 -> conflict-free frags
    __shared__ float Bs[2][16][72];    // [k][n], stride 72

    const int tid = threadIdx.x;
    const int bm = blockIdx.y * 128;
    const int bn = blockIdx.x * 64;
    const int warp = tid >> 5;
    const int warpm = warp & 3;        // 0..3 -> M offset warpm*32
    const int warpn = warp >> 2;       // 0..1 -> N offset warpn*32
    const int lane = tid & 31;
    const int lr = lane >> 2;          // groupID 0..7
    const int lc = lane & 3;           // threadID_in_group 0..3

    const int nTiles = (K + 15) >> 4;

    float acc[2][4][4];
#pragma unroll
    for (int mi = 0; mi < 2; mi++)
#pragma unroll
        for (int ni = 0; ni < 4; ni++)
#pragma unroll
            for (int r = 0; r < 4; r++) acc[mi][ni][r] = 0.f;

    // ---- tile loaders (global -> regs, tf32-rounded) ----
    auto loadTile = [&](int t, float* ra, float* rb) {
        int k0 = t << 4;
#pragma unroll
        for (int i = 0; i < 8; i++) {          // A: 128x16 = 2048 elems
            int idx = tid + i * 256;
            int m = idx >> 4, kk = idx & 15;
            int kg = k0 + kk;
            float v = 0.f;
            if (kg < K) {
                if (A2 && kg >= Ksplit)
                    v = A2[(long)(bm + m) * lda + (kg - Ksplit)];
                else
                    v = A[(long)(bm + m) * lda + kg];
            }
            ra[i] = to_tf32(v);
        }
        if (!transB) {
#pragma unroll
            for (int i = 0; i < 4; i++) {      // B: 16x64 = 1024 elems
                int idx = tid + i * 256;
                int kk = idx >> 6, n = idx & 63;
                int kg = k0 + kk;
                float v = (kg < K) ? B[(long)kg * ldb + bn + n] : 0.f;
                rb[i] = to_tf32(v);
            }
        } else {
#pragma unroll
            for (int i = 0; i < 4; i++) {
                int idx = tid + i * 256;
                int kk = idx & 15, n = idx >> 4;
                int kg = k0 + kk;
                float v = (kg < K) ? B[(long)(bn + n) * ldb + kg] : 0.f;
                rb[i] = to_tf32(v);
            }
        }
    };
    auto storeTile = [&](int st, const float* ra, const float* rb) {
#pragma unroll
        for (int i = 0; i < 8; i++) {
            int idx = tid + i * 256;
            int m = idx >> 4, kk = idx & 15;
            As[st][kk][m] = ra[i];
        }
        if (!transB) {
#pragma unroll
            for (int i = 0; i < 4; i++) {
                int idx = tid + i * 256;
                int kk = idx >> 6, n = idx & 63;
                Bs[st][kk][n] = rb[i];
            }
        } else {
#pragma unroll
            for (int i = 0; i < 4; i++) {
                int idx = tid + i * 256;
                int kk = idx & 15, n = idx >> 4;
                Bs[st][kk][n] = rb[i];
            }
        }
    };

    // preload stage 0
    {
        float ra[8], rb[4];
        loadTile(0, ra, rb);
        storeTile(0, ra, rb);
    }
    __syncthreads();

    for (int t = 0; t < nTiles; t++) {
        const int cur = t & 1;
        const bool hasNext = (t + 1 < nTiles);
        float ra[8], rb[4];
        if (hasNext) loadTile(t + 1, ra, rb);

#pragma unroll
        for (int ks = 0; ks < 2; ks++) {
            const int kb = ks * 8;
            unsigned af[2][4];
#pragma unroll
            for (int mi = 0; mi < 2; mi++) {
                int mo = warpm * 32 + mi * 16 + lr;
                af[mi][0] = __float_as_uint(As[cur][kb + lc][mo]);
                af[mi][1] = __float_as_uint(As[cur][kb + lc][mo + 8]);
                af[mi][2] = __float_as_uint(As[cur][kb + lc + 4][mo]);
                af[mi][3] = __float_as_uint(As[cur][kb + lc + 4][mo + 8]);
            }
            unsigned bf[4][2];
#pragma unroll
            for (int ni = 0; ni < 4; ni++) {
                int no = warpn * 32 + ni * 8 + lr;
                bf[ni][0] = __float_as_uint(Bs[cur][kb + lc][no]);
                bf[ni][1] = __float_as_uint(Bs[cur][kb + lc + 4][no]);
            }
#pragma unroll
            for (int mi = 0; mi < 2; mi++)
#pragma unroll
                for (int ni = 0; ni < 4; ni++)
                    MMA_TF32(acc[mi][ni], af[mi], bf[ni]);
        }

        if (hasNext) storeTile((t + 1) & 1, ra, rb);
        __syncthreads();
    }

    // ---- epilogue ----
    float cv = 0.f;
    const float* prevp = nullptr;
    const float* maskp = nullptr;
    if (epi) {
        maskp = mask + (long)bb * N;
        if (epi == 2) {
            cv = cvec[cidx];
            prevp = prev + (long)z * (long)M * N;
        }
    }

#pragma unroll
    for (int mi = 0; mi < 2; mi++) {
#pragma unroll
        for (int ni = 0; ni < 4; ni++) {
            int row0 = bm + warpm * 32 + mi * 16 + lr;
            int col = bn + warpn * 32 + ni * 8 + lc * 2;
#pragma unroll
            for (int rr = 0; rr < 2; rr++) {
                int row = row0 + rr * 8;
                float v0 = acc[mi][ni][rr * 2 + 0];
                float v1 = acc[mi][ni][rr * 2 + 1];
                if (epi) {
                    v0 *= 0.125f;
                    v1 *= 0.125f;
                    if (prevp) {
                        v0 += cv * prevp[(long)row * N + col];
                        v1 += cv * prevp[(long)row * N + col + 1];
                    }
                    v0 -= 1e8f * (1.f - maskp[col]);
                    v1 -= 1e8f * (1.f - maskp[col + 1]);
                }
                C[(long)row * ldc + col] = v0;
                C[(long)row * ldc + col + 1] = v1;
            }
        }
    }
}

// ---------------------------------------------------------------------------
// Row softmax over 512 (one block per row). src may equal dst.
// ---------------------------------------------------------------------------
__global__ void __launch_bounds__(256) softmax_kernel(
    const float* __restrict__ src, float* __restrict__ dst)
{
    long row = blockIdx.x;
    const float* p = src + row * SEQ;
    float* q = dst + row * SEQ;
    int tid = threadIdx.x;
    float v0 = p[tid], v1 = p[tid + 256];

    __shared__ float red[256];
    red[tid] = fmaxf(v0, v1);
    __syncthreads();
    for (int s = 128; s > 0; s >>= 1) {
        if (tid < s) red[tid] = fmaxf(red[tid], red[tid + s]);
        __syncthreads();
    }
    float m = red[0];
    __syncthreads();

    float e0 = expf(v0 - m), e1 = expf(v1 - m);
    red[tid] = e0 + e1;
    __syncthreads();
    for (int s = 128; s > 0; s >>= 1) {
        if (tid < s) red[tid] += red[tid + s];
        __syncthreads();
    }
    float inv = 1.f / red[0];
    q[tid] = e0 * inv;
    q[tid + 256] = e1 * inv;
}

// ---------------------------------------------------------------------------
// LayerNorm over last dim 512 (one block per row).
// ---------------------------------------------------------------------------
__global__ void __launch_bounds__(256) ln_kernel(
    const float* __restrict__ X, float* __restrict__ Y,
    const float* __restrict__ g, const float* __restrict__ b)
{
    long row = blockIdx.x;
    const float* x = X + row * DIM;
    float* y = Y + row * DIM;
    int tid = threadIdx.x;
    float v0 = x[tid], v1 = x[tid + 256];

    __shared__ float red[256];
    red[tid] = v0 + v1;
    __syncthreads();
    for (int s = 128; s > 0; s >>= 1) {
        if (tid < s) red[tid] += red[tid + s];
        __syncthreads();
    }
    float mu = red[0] * (1.f / DIM);
    __syncthreads();

    float d0 = v0 - mu, d1 = v1 - mu;
    red[tid] = d0 * d0 + d1 * d1;
    __syncthreads();
    for (int s = 128; s > 0; s >>= 1) {
        if (tid < s) red[tid] += red[tid + s];
        __syncthreads();
    }
    float rstd = rsqrtf(red[0] * (1.f / DIM) + 1e-5f);

    y[tid] = d0 * rstd * g[tid] + b[tid];
    y[tid + 256] = d1 * rstd * g[tid + 256] + b[tid + 256];
}

// ---------------------------------------------------------------------------
// Pooling
// ---------------------------------------------------------------------------
__global__ void pool_init(float* s, float* m, int n)
{
    int i = blockIdx.x * blockDim.x + threadIdx.x;
    if (i < n) { s[i] = 0.f; m[i] = -INFINITY; }
}

__global__ void __launch_bounds__(256) pool_reduce(
    const float* __restrict__ O, float* __restrict__ sum, float* __restrict__ mx)
{
    int idx = blockIdx.x * 256 + threadIdx.x;   // 0..4095 -> (b, d)
    int bb = idx >> 9, d = idx & 511;
    const float* p = O + (long)bb * (SEQ * DIM) + d;
    float s = 0.f, m = -INFINITY;
#pragma unroll 4
    for (int r = 0; r < SEQ; r++) {
        float v = p[(long)r * DIM];
        s += v;
        m = fmaxf(m, v);
    }
    sum[idx] += s;
    mx[idx] = fmaxf(mx[idx], m);
}

// ---------------------------------------------------------------------------
// Classifier: out[b,c] = sum_j mean[b,j]*W[j,c] + max[b,j]*W[3072+j,c]
// ---------------------------------------------------------------------------
__global__ void __launch_bounds__(256) clf_kernel(
    const float* __restrict__ sum, const float* __restrict__ mx,
    const float* __restrict__ W, float* __restrict__ out)
{
    int bb = blockIdx.x / 9, cls = blockIdx.x % 9;
    int tid = threadIdx.x;
    float acc = 0.f;
    for (int j = tid; j < 3072; j += 256) {
        int k = j >> 9, d = j & 511;
        float sm = sum[k * 4096 + bb * 512 + d] * (1.f / 1536.f);
        float mv = mx[k * 4096 + bb * 512 + d];
        acc += sm * W[(long)j * 9 + cls] + mv * W[(long)(3072 + j) * 9 + cls];
    }
    __shared__ float red[256];
    red[tid] = acc;
    __syncthreads();
    for (int s = 128; s > 0; s >>= 1) {
        if (tid < s) red[tid] += red[tid + s];
        __syncthreads();
    }
    if (tid == 0) out[bb * 9 + cls] = red[0];
}

// ---------------------------------------------------------------------------
// Host orchestration
// ---------------------------------------------------------------------------
extern "C" void kernel_launch(void* const* d_in, const int* in_sizes, int n_in,
                              void* d_out, int out_size)
{
    const float* l      = (const float*)d_in[0];
    const float* v      = (const float*)d_in[1];
    const float* a      = (const float*)d_in[2];
    const float* l_mask = (const float*)d_in[3];
    const float* v_mask = (const float*)d_in[4];
    const float* a_mask = (const float*)d_in[5];
    const float* wl     = (const float*)d_in[6];
    const float* wv     = (const float*)d_in[7];
    const float* wa     = (const float*)d_in[8];
    const float* n1_g   = (const float*)d_in[9];
    const float* n1_b   = (const float*)d_in[10];
    const float* proj_w = (const float*)d_in[11];
    const float* minus_w= (const float*)d_in[12];
    const float* n2_g   = (const float*)d_in[13];
    const float* n2_b   = (const float*)d_in[14];
    const float* cvec   = (const float*)d_in[15];
    const float* clf_w  = (const float*)d_in[16];
    float* out          = (float*)d_out;

    float *pU0, *pU1, *pU2, *pq0, *pq1, *pctx, *px, *ptmp, *pS, *pP, *psum, *pmax;
    cudaGetSymbolAddress((void**)&pU0, g_U0);
    cudaGetSymbolAddress((void**)&pU1, g_U1);
    cudaGetSymbolAddress((void**)&pU2, g_U2);
    cudaGetSymbolAddress((void**)&pq0, g_q0);
    cudaGetSymbolAddress((void**)&pq1, g_q1);
    cudaGetSymbolAddress((void**)&pctx, g_ctx);
    cudaGetSymbolAddress((void**)&px, g_x);
    cudaGetSymbolAddress((void**)&ptmp, g_tmp);
    cudaGetSymbolAddress((void**)&pS, g_S);
    cudaGetSymbolAddress((void**)&pP, g_P);
    cudaGetSymbolAddress((void**)&psum, g_sum);
    cudaGetSymbolAddress((void**)&pmax, g_max);

    const int M = BATCH * SEQ;   // 4096

    pool_init<<<96, 256>>>(psum, pmax, 6 * BATCH * DIM);

    // --- Unify + LN ---
    const float* uin[3] = { l, v, a };
    const float* uw[3]  = { wl, wv, wa };
    const int    uk[3]  = { 768, 640, 205 };
    float* U[3] = { pU0, pU1, pU2 };
    for (int m = 0; m < 3; m++) {
        mma_gemm<<<dim3(DIM / 64, M / 128, 1), 256>>>(
            uin[m], nullptr, 1 << 30, uw[m], 0, ptmp,
            M, DIM, uk[m], uk[m], DIM, DIM,
            1, 0, 0, 0, 0, 0, 0,
            0, nullptr, nullptr, nullptr, 0);
        ln_kernel<<<M, 256>>>(ptmp, U[m], n1_g, n1_b);
    }

    // --- 9 streams x 2 layers ---
    const int qsrc[9] = { 0, 0, 0, 1, 1, 1, 2, 2, 2 };
    const int kvi[9]  = { 0, 1, 2, 1, 0, 2, 2, 0, 1 };
    const float* masks[3] = { l_mask, v_mask, a_mask };

    for (int off = 0; off < 9; off++) {
        const float* kv  = U[kvi[off]];
        const float* msk = masks[kvi[off]];
        const float* qin = U[qsrc[off]];
        float* qouts[2] = { pq0, pq1 };

        for (int j = 0; j < 2; j++) {
            int i = off * 2 + j;
            float* Sout = (j == 0) ? pS : pP;

            // scores (NT) + fused scale / residual / mask epilogue
            mma_gemm<<<dim3(SEQ / 64, SEQ / 128, BATCH * NH), 256>>>(
                qin, nullptr, 1 << 30, kv, 1, Sout,
                SEQ, SEQ, HD, DIM, DIM, SEQ,
                NH,
                (long)SEQ * DIM, (long)HD,          // A (Q) strides
                (long)SEQ * DIM, (long)HD,          // B (K) strides
                (long)NH * SEQ * SEQ, (long)SEQ * SEQ,  // C strides
                (j == 0) ? 1 : 2, pS, msk, cvec, i);

            // softmax: layer0 S->P (keep S), layer1 in-place on P
            softmax_kernel<<<BATCH * NH * SEQ, 256>>>(Sout, pP);

            // ctx[b,q,h*64+d] = P[b,h] @ kv_head
            mma_gemm<<<dim3(HD / 64, SEQ / 128, BATCH * NH), 256>>>(
                pP, nullptr, 1 << 30, kv, 0, pctx,
                SEQ, HD, SEQ, SEQ, DIM, DIM,
                NH,
                (long)NH * SEQ * SEQ, (long)SEQ * SEQ,
                (long)SEQ * DIM, (long)HD,
                (long)SEQ * DIM, (long)HD,
                0, nullptr, nullptr, nullptr, 0);

            // x = ctx @ proj_w[i]
            mma_gemm<<<dim3(DIM / 64, M / 128, 1), 256>>>(
                pctx, nullptr, 1 << 30, proj_w + (long)i * DIM * DIM, 0, px,
                M, DIM, DIM, DIM, DIM, DIM,
                1, 0, 0, 0, 0, 0, 0,
                0, nullptr, nullptr, nullptr, 0);

            // tmp = [qin, x] @ minus_w[i]   (split-A concat GEMM)
            mma_gemm<<<dim3(DIM / 64, M / 128, 1), 256>>>(
                qin, px, DIM, minus_w + (long)i * 2 * DIM * DIM, 0, ptmp,
                M, DIM, 2 * DIM, DIM, DIM, DIM,
                1, 0, 0, 0, 0, 0, 0,
                0, nullptr, nullptr, nullptr, 0);

            // LN -> new q
            float* qout = qouts[j];
            ln_kernel<<<M, 256>>>(ptmp, qout, n2_g + (long)i * DIM, n2_b + (long)i * DIM);

            // pool into slot k
            int k = (off % 3) * 2 + j;
            pool_reduce<<<16, 256>>>(qout, psum + (long)k * 4096, pmax + (long)k * 4096);

            qin = qout;
        }
    }

    clf_kernel<<<BATCH * 9, 256>>>(psum, pmax, clf_w, out);
}

// round 5
// speedup vs baseline: 4.4631x; 1.9705x over previous
#include <cuda_runtime.h>
#include <math.h>

// ---------------------------------------------------------------------------
// Problem constants
// ---------------------------------------------------------------------------
#define BATCH 8
#define NH 8
#define SEQ 512
#define DIM 512
#define HD 64

// ---------------------------------------------------------------------------
// Scratch (device globals; no allocations allowed)
// ---------------------------------------------------------------------------
__device__ float g_U0[BATCH * SEQ * DIM];
__device__ float g_U1[BATCH * SEQ * DIM];
__device__ float g_U2[BATCH * SEQ * DIM];
__device__ float g_q0[BATCH * SEQ * DIM];
__device__ float g_q1[BATCH * SEQ * DIM];
__device__ float g_ctx[BATCH * SEQ * DIM];
__device__ float g_tmp[BATCH * SEQ * DIM];
__device__ float g_S[BATCH * NH * SEQ * SEQ];   // layer-0 scores (post-mask)
__device__ float g_P[BATCH * NH * SEQ * SEQ];   // probs / layer-1 scores
__device__ float g_W[18 * DIM * DIM];           // precomputed proj@minus_bottom
__device__ float g_sum[6 * BATCH * DIM];
__device__ float g_max[6 * BATCH * DIM];

// ---------------------------------------------------------------------------
// MMA / cp.async helpers
// ---------------------------------------------------------------------------
#define MMA_TF32(d, a, b)                                                     \
    asm volatile(                                                             \
        "mma.sync.aligned.m16n8k8.row.col.f32.tf32.tf32.f32 "                 \
        "{%0,%1,%2,%3},{%4,%5,%6,%7},{%8,%9},{%0,%1,%2,%3};"                  \
        : "+f"(d[0]), "+f"(d[1]), "+f"(d[2]), "+f"(d[3])                      \
        : "r"(a[0]), "r"(a[1]), "r"(a[2]), "r"(a[3]), "r"(b[0]), "r"(b[1]))

__device__ __forceinline__ void cp16(unsigned dst, const float* src)
{
    asm volatile("cp.async.cg.shared.global [%0], [%1], 16;"
                 :: "r"(dst), "l"(src));
}

// ---------------------------------------------------------------------------
// Pipelined TF32 tensor-core GEMM (cp.async 3-stage).
//   C[M,N] = op(A) @ op(B), A row-major [M,K].
//   TRANSB=0: B row-major [K,N];  TRANSB=1: B row-major [N,K] (C = A@B^T).
//   SPLIT: for k >= Ksplit, A-source = A2 and B-source = B2 (cols rebased).
//   EPI: 0 plain; 1 scores L0 (scale+mask); 2 scores L1 (+ c*prev).
// CTA tile 128x64x16, 8 warps (warp 32x32), requires K%16==0, lda%4==0,
// M%128==0, N%64==0, 16B-aligned base pointers.  Batched over blockIdx.z.
// ---------------------------------------------------------------------------
template<int EPI, bool TRANSB, bool SPLIT>
__global__ void __launch_bounds__(256) tc_gemm(
    const float* __restrict__ A, const float* __restrict__ A2,
    const float* __restrict__ B, const float* __restrict__ B2, int Ksplit,
    float* __restrict__ C,
    int M, int N, int K, int lda, int ldb, int ldc,
    int H, long sAb, long sAh, long sBb, long sBh, long sCb, long sCh,
    const float* __restrict__ prev, const float* __restrict__ mask,
    const float* __restrict__ cvec, int cidx)
{
    __shared__ float As[3][128 * 20];   // [m][k] rows padded to 20 floats
    __shared__ float Bs[3][1280];       // NN: [k][72]; NT: [n][20]

    const int z = blockIdx.z;
    const int bb = z / H, hh = z - bb * H;
    A += (long)bb * sAb + (long)hh * sAh;
    if (SPLIT) A2 += (long)bb * sAb + (long)hh * sAh;
    B += (long)bb * sBb + (long)hh * sBh;
    C += (long)bb * sCb + (long)hh * sCh;

    const int tid = threadIdx.x;
    const int bm = blockIdx.y * 128;
    const int bn = blockIdx.x * 64;
    const int warp = tid >> 5;
    const int warpm = warp & 3, warpn = warp >> 2;
    const int lane = tid & 31;
    const int lr = lane >> 2, lc = lane & 3;
    const int nT = K >> 4;

    // ---- staging thread offsets (hoisted) ----
    const int ar = tid >> 2;                 // A rows ar, ar+64
    const int aj = (tid & 3) << 2;           // A k-granule
    const long aoff0 = (long)(bm + ar) * lda + aj;
    const long aoff1 = (long)(bm + ar + 64) * lda + aj;

    long boffg;
    if (!TRANSB) boffg = (long)(tid >> 4) * ldb + bn + ((tid & 15) << 2);
    else         boffg = (long)(bn + (tid >> 2)) * ldb + ((tid & 3) << 2);

    const unsigned asb = (unsigned)__cvta_generic_to_shared(As);
    const unsigned bsb = (unsigned)__cvta_generic_to_shared(Bs);
    const unsigned sa0 = asb + (unsigned)(ar * 20 + aj) * 4u;
    const unsigned sa1 = asb + (unsigned)((ar + 64) * 20 + aj) * 4u;
    unsigned sb0;
    if (!TRANSB) sb0 = bsb + (unsigned)((tid >> 4) * 72 + ((tid & 15) << 2)) * 4u;
    else         sb0 = bsb + (unsigned)((tid >> 2) * 20 + ((tid & 3) << 2)) * 4u;

    auto load_tile = [&](int t, int s) {
        int k0 = t << 4;
        const float* Ab = A; const float* Bb = B; int kk = k0;
        if (SPLIT && k0 >= Ksplit) { Ab = A2; Bb = B2; kk = k0 - Ksplit; }
        unsigned oa = (unsigned)s * (128 * 20 * 4u);
        unsigned ob = (unsigned)s * (1280 * 4u);
        cp16(sa0 + oa, Ab + aoff0 + kk);
        cp16(sa1 + oa, Ab + aoff1 + kk);
        if (!TRANSB) cp16(sb0 + ob, Bb + (long)kk * ldb + boffg);
        else         cp16(sb0 + ob, Bb + boffg + kk);
    };

    // prologue: stages 0,1
#pragma unroll
    for (int s = 0; s < 2; s++) {
        if (s < nT) load_tile(s, s);
        asm volatile("cp.async.commit_group;");
    }

    float acc[2][4][4] = {};

    // fragment smem bases (floats)
    const int afb = (warpm * 32 + lr) * 20 + lc;            // +mi*320, +160, +4, +ks*8
    int bfb;
    if (!TRANSB) bfb = lc * 72 + warpn * 32 + lr;           // +ni*8, +288, +ks*576
    else         bfb = (warpn * 32 + lr) * 20 + lc;         // +ni*160, +4, +ks*8

    for (int t = 0; t < nT; t++) {
        asm volatile("cp.async.wait_group 1;");
        __syncthreads();
        if (t + 2 < nT) load_tile(t + 2, (t + 2) % 3);
        asm volatile("cp.async.commit_group;");

        const float* as = As[t % 3];
        const float* bs = Bs[t % 3];
#pragma unroll
        for (int ks = 0; ks < 2; ks++) {
            unsigned af[2][4];
#pragma unroll
            for (int mi = 0; mi < 2; mi++) {
                int base = afb + mi * 320 + ks * 8;
                af[mi][0] = __float_as_uint(as[base]);
                af[mi][1] = __float_as_uint(as[base + 160]);
                af[mi][2] = __float_as_uint(as[base + 4]);
                af[mi][3] = __float_as_uint(as[base + 164]);
            }
            unsigned bf[4][2];
#pragma unroll
            for (int ni = 0; ni < 4; ni++) {
                if (!TRANSB) {
                    int base = bfb + ni * 8 + ks * 576;
                    bf[ni][0] = __float_as_uint(bs[base]);
                    bf[ni][1] = __float_as_uint(bs[base + 288]);
                } else {
                    int base = bfb + ni * 160 + ks * 8;
                    bf[ni][0] = __float_as_uint(bs[base]);
                    bf[ni][1] = __float_as_uint(bs[base + 4]);
                }
            }
#pragma unroll
            for (int mi = 0; mi < 2; mi++)
#pragma unroll
                for (int ni = 0; ni < 4; ni++)
                    MMA_TF32(acc[mi][ni], af[mi], bf[ni]);
        }
    }

    // ---- epilogue ----
    float cv = 0.f;
    const float* prevp = nullptr;
    const float* maskp = nullptr;
    if (EPI) {
        maskp = mask + (long)bb * N;
        if (EPI == 2) {
            cv = cvec[cidx];
            prevp = prev + (long)z * M * N;
        }
    }

#pragma unroll
    for (int mi = 0; mi < 2; mi++)
#pragma unroll
        for (int ni = 0; ni < 4; ni++) {
            int row0 = bm + warpm * 32 + mi * 16 + lr;
            int col = bn + warpn * 32 + ni * 8 + lc * 2;
#pragma unroll
            for (int rr = 0; rr < 2; rr++) {
                int row = row0 + rr * 8;
                float v0 = acc[mi][ni][rr * 2 + 0];
                float v1 = acc[mi][ni][rr * 2 + 1];
                if (EPI) {
                    v0 *= 0.125f;
                    v1 *= 0.125f;
                    if (EPI == 2) {
                        v0 += cv * prevp[(long)row * N + col];
                        v1 += cv * prevp[(long)row * N + col + 1];
                    }
                    v0 -= 1e8f * (1.f - maskp[col]);
                    v1 -= 1e8f * (1.f - maskp[col + 1]);
                }
                *(float2*)&C[(long)row * ldc + col] = make_float2(v0, v1);
            }
        }
}

// ---------------------------------------------------------------------------
// Fallback TF32 GEMM (from round 3, verified) — used only for unify-a
// (K=205, lda=205: unaligned for cp.async). Plain NN, no epilogue.
// ---------------------------------------------------------------------------
__device__ __forceinline__ float to_tf32(float x)
{
    unsigned u;
    asm("cvt.rna.tf32.f32 %0, %1;" : "=r"(u) : "f"(x));
    return __uint_as_float(u);
}

__global__ void __launch_bounds__(256) gen_gemm(
    const float* __restrict__ A, const float* __restrict__ B,
    float* __restrict__ C, int M, int N, int K, int lda, int ldb, int ldc)
{
    __shared__ float As[2][16][136];
    __shared__ float Bs[2][16][72];

    const int tid = threadIdx.x;
    const int bm = blockIdx.y * 128;
    const int bn = blockIdx.x * 64;
    const int warp = tid >> 5;
    const int warpm = warp & 3;
    const int warpn = warp >> 2;
    const int lane = tid & 31;
    const int lr = lane >> 2;
    const int lc = lane & 3;
    const int nTiles = (K + 15) >> 4;

    float acc[2][4][4] = {};

    auto loadTile = [&](int t, float* ra, float* rb) {
        int k0 = t << 4;
#pragma unroll
        for (int i = 0; i < 8; i++) {
            int idx = tid + i * 256;
            int m = idx >> 4, kk = idx & 15;
            int kg = k0 + kk;
            float v = (kg < K) ? A[(long)(bm + m) * lda + kg] : 0.f;
            ra[i] = to_tf32(v);
        }
#pragma unroll
        for (int i = 0; i < 4; i++) {
            int idx = tid + i * 256;
            int kk = idx >> 6, n = idx & 63;
            int kg = k0 + kk;
            float v = (kg < K) ? B[(long)kg * ldb + bn + n] : 0.f;
            rb[i] = to_tf32(v);
        }
    };
    auto storeTile = [&](int st, const float* ra, const float* rb) {
#pragma unroll
        for (int i = 0; i < 8; i++) {
            int idx = tid + i * 256;
            As[st][idx & 15][idx >> 4] = ra[i];
        }
#pragma unroll
        for (int i = 0; i < 4; i++) {
            int idx = tid + i * 256;
            Bs[st][idx >> 6][idx & 63] = rb[i];
        }
    };

    {
        float ra[8], rb[4];
        loadTile(0, ra, rb);
        storeTile(0, ra, rb);
    }
    __syncthreads();

    for (int t = 0; t < nTiles; t++) {
        const int cur = t & 1;
        const bool hasNext = (t + 1 < nTiles);
        float ra[8], rb[4];
        if (hasNext) loadTile(t + 1, ra, rb);

#pragma unroll
        for (int ks = 0; ks < 2; ks++) {
            const int kb = ks * 8;
            unsigned af[2][4];
#pragma unroll
            for (int mi = 0; mi < 2; mi++) {
                int mo = warpm * 32 + mi * 16 + lr;
                af[mi][0] = __float_as_uint(As[cur][kb + lc][mo]);
                af[mi][1] = __float_as_uint(As[cur][kb + lc][mo + 8]);
                af[mi][2] = __float_as_uint(As[cur][kb + lc + 4][mo]);
                af[mi][3] = __float_as_uint(As[cur][kb + lc + 4][mo + 8]);
            }
            unsigned bf[4][2];
#pragma unroll
            for (int ni = 0; ni < 4; ni++) {
                int no = warpn * 32 + ni * 8 + lr;
                bf[ni][0] = __float_as_uint(Bs[cur][kb + lc][no]);
                bf[ni][1] = __float_as_uint(Bs[cur][kb + lc + 4][no]);
            }
#pragma unroll
            for (int mi = 0; mi < 2; mi++)
#pragma unroll
                for (int ni = 0; ni < 4; ni++)
                    MMA_TF32(acc[mi][ni], af[mi], bf[ni]);
        }

        if (hasNext) storeTile((t + 1) & 1, ra, rb);
        __syncthreads();
    }

#pragma unroll
    for (int mi = 0; mi < 2; mi++)
#pragma unroll
        for (int ni = 0; ni < 4; ni++) {
            int row0 = bm + warpm * 32 + mi * 16 + lr;
            int col = bn + warpn * 32 + ni * 8 + lc * 2;
#pragma unroll
            for (int rr = 0; rr < 2; rr++) {
                int row = row0 + rr * 8;
                C[(long)row * ldc + col] = acc[mi][ni][rr * 2 + 0];
                C[(long)row * ldc + col + 1] = acc[mi][ni][rr * 2 + 1];
            }
        }
}

// ---------------------------------------------------------------------------
// Row softmax over 512 (one block per row). src may equal dst.
// ---------------------------------------------------------------------------
__global__ void __launch_bounds__(256) softmax_kernel(
    const float* __restrict__ src, float* __restrict__ dst)
{
    long row = blockIdx.x;
    const float* p = src + row * SEQ;
    float* q = dst + row * SEQ;
    int tid = threadIdx.x;
    float v0 = p[tid], v1 = p[tid + 256];

    __shared__ float red[256];
    red[tid] = fmaxf(v0, v1);
    __syncthreads();
    for (int s = 128; s > 0; s >>= 1) {
        if (tid < s) red[tid] = fmaxf(red[tid], red[tid + s]);
        __syncthreads();
    }
    float m = red[0];
    __syncthreads();

    float e0 = expf(v0 - m), e1 = expf(v1 - m);
    red[tid] = e0 + e1;
    __syncthreads();
    for (int s = 128; s > 0; s >>= 1) {
        if (tid < s) red[tid] += red[tid + s];
        __syncthreads();
    }
    float inv = 1.f / red[0];
    q[tid] = e0 * inv;
    q[tid + 256] = e1 * inv;
}

// ---------------------------------------------------------------------------
// LayerNorm over last dim 512 (one block per row).
// ---------------------------------------------------------------------------
__global__ void __launch_bounds__(256) ln_kernel(
    const float* __restrict__ X, float* __restrict__ Y,
    const float* __restrict__ g, const float* __restrict__ b)
{
    long row = blockIdx.x;
    const float* x = X + row * DIM;
    float* y = Y + row * DIM;
    int tid = threadIdx.x;
    float v0 = x[tid], v1 = x[tid + 256];

    __shared__ float red[256];
    red[tid] = v0 + v1;
    __syncthreads();
    for (int s = 128; s > 0; s >>= 1) {
        if (tid < s) red[tid] += red[tid + s];
        __syncthreads();
    }
    float mu = red[0] * (1.f / DIM);
    __syncthreads();

    float d0 = v0 - mu, d1 = v1 - mu;
    red[tid] = d0 * d0 + d1 * d1;
    __syncthreads();
    for (int s = 128; s > 0; s >>= 1) {
        if (tid < s) red[tid] += red[tid + s];
        __syncthreads();
    }
    float rstd = rsqrtf(red[0] * (1.f / DIM) + 1e-5f);

    y[tid] = d0 * rstd * g[tid] + b[tid];
    y[tid + 256] = d1 * rstd * g[tid + 256] + b[tid + 256];
}

// ---------------------------------------------------------------------------
// Pooling
// ---------------------------------------------------------------------------
__global__ void pool_init(float* s, float* m, int n)
{
    int i = blockIdx.x * blockDim.x + threadIdx.x;
    if (i < n) { s[i] = 0.f; m[i] = -INFINITY; }
}

__global__ void __launch_bounds__(256) pool_reduce(
    const float* __restrict__ O, float* __restrict__ sum, float* __restrict__ mx)
{
    int idx = blockIdx.x * 256 + threadIdx.x;   // 0..4095 -> (b, d)
    int bb = idx >> 9, d = idx & 511;
    const float* p = O + (long)bb * (SEQ * DIM) + d;
    float s = 0.f, m = -INFINITY;
#pragma unroll 4
    for (int r = 0; r < SEQ; r++) {
        float v = p[(long)r * DIM];
        s += v;
        m = fmaxf(m, v);
    }
    sum[idx] += s;
    mx[idx] = fmaxf(mx[idx], m);
}

// ---------------------------------------------------------------------------
// Classifier
// ---------------------------------------------------------------------------
__global__ void __launch_bounds__(256) clf_kernel(
    const float* __restrict__ sum, const float* __restrict__ mx,
    const float* __restrict__ W, float* __restrict__ out)
{
    int bb = blockIdx.x / 9, cls = blockIdx.x % 9;
    int tid = threadIdx.x;
    float acc = 0.f;
    for (int j = tid; j < 3072; j += 256) {
        int k = j >> 9, d = j & 511;
        float sm = sum[k * 4096 + bb * 512 + d] * (1.f / 1536.f);
        float mv = mx[k * 4096 + bb * 512 + d];
        acc += sm * W[(long)j * 9 + cls] + mv * W[(long)(3072 + j) * 9 + cls];
    }
    __shared__ float red[256];
    red[tid] = acc;
    __syncthreads();
    for (int s = 128; s > 0; s >>= 1) {
        if (tid < s) red[tid] += red[tid + s];
        __syncthreads();
    }
    if (tid == 0) out[bb * 9 + cls] = red[0];
}

// ---------------------------------------------------------------------------
// Host orchestration
// ---------------------------------------------------------------------------
extern "C" void kernel_launch(void* const* d_in, const int* in_sizes, int n_in,
                              void* d_out, int out_size)
{
    const float* l      = (const float*)d_in[0];
    const float* v      = (const float*)d_in[1];
    const float* a      = (const float*)d_in[2];
    const float* l_mask = (const float*)d_in[3];
    const float* v_mask = (const float*)d_in[4];
    const float* a_mask = (const float*)d_in[5];
    const float* wl     = (const float*)d_in[6];
    const float* wv     = (const float*)d_in[7];
    const float* wa     = (const float*)d_in[8];
    const float* n1_g   = (const float*)d_in[9];
    const float* n1_b   = (const float*)d_in[10];
    const float* proj_w = (const float*)d_in[11];
    const float* minus_w= (const float*)d_in[12];
    const float* n2_g   = (const float*)d_in[13];
    const float* n2_b   = (const float*)d_in[14];
    const float* cvec   = (const float*)d_in[15];
    const float* clf_w  = (const float*)d_in[16];
    float* out          = (float*)d_out;

    float *pU0, *pU1, *pU2, *pq0, *pq1, *pctx, *ptmp, *pS, *pP, *pW, *psum, *pmax;
    cudaGetSymbolAddress((void**)&pU0, g_U0);
    cudaGetSymbolAddress((void**)&pU1, g_U1);
    cudaGetSymbolAddress((void**)&pU2, g_U2);
    cudaGetSymbolAddress((void**)&pq0, g_q0);
    cudaGetSymbolAddress((void**)&pq1, g_q1);
    cudaGetSymbolAddress((void**)&pctx, g_ctx);
    cudaGetSymbolAddress((void**)&ptmp, g_tmp);
    cudaGetSymbolAddress((void**)&pS, g_S);
    cudaGetSymbolAddress((void**)&pP, g_P);
    cudaGetSymbolAddress((void**)&pW, g_W);
    cudaGetSymbolAddress((void**)&psum, g_sum);
    cudaGetSymbolAddress((void**)&pmax, g_max);

    const int M = BATCH * SEQ;   // 4096

    pool_init<<<96, 256>>>(psum, pmax, 6 * BATCH * DIM);

    // --- precompute W[i] = proj_w[i] @ minus_w[i][512:1024] (batched, 18) ---
    tc_gemm<0, false, false><<<dim3(DIM / 64, DIM / 128, 18), 256>>>(
        proj_w, nullptr, minus_w + (long)DIM * DIM, nullptr, 0, pW,
        DIM, DIM, DIM, DIM, DIM, DIM,
        1, (long)DIM * DIM, 0, (long)2 * DIM * DIM, 0, (long)DIM * DIM, 0,
        nullptr, nullptr, nullptr, 0);

    // --- Unify + LN ---
    float* U[3] = { pU0, pU1, pU2 };
    // l: K=768 (aligned)
    tc_gemm<0, false, false><<<dim3(DIM / 64, M / 128, 1), 256>>>(
        l, nullptr, wl, nullptr, 0, ptmp,
        M, DIM, 768, 768, DIM, DIM,
        1, 0, 0, 0, 0, 0, 0, nullptr, nullptr, nullptr, 0);
    ln_kernel<<<M, 256>>>(ptmp, pU0, n1_g, n1_b);
    // v: K=640 (aligned)
    tc_gemm<0, false, false><<<dim3(DIM / 64, M / 128, 1), 256>>>(
        v, nullptr, wv, nullptr, 0, ptmp,
        M, DIM, 640, 640, DIM, DIM,
        1, 0, 0, 0, 0, 0, 0, nullptr, nullptr, nullptr, 0);
    ln_kernel<<<M, 256>>>(ptmp, pU1, n1_g, n1_b);
    // a: K=205 (unaligned) -> fallback
    gen_gemm<<<dim3(DIM / 64, M / 128, 1), 256>>>(
        a, wa, ptmp, M, DIM, 205, 205, DIM, DIM);
    ln_kernel<<<M, 256>>>(ptmp, pU2, n1_g, n1_b);

    // --- 9 streams x 2 layers ---
    const int qsrc[9] = { 0, 0, 0, 1, 1, 1, 2, 2, 2 };
    const int kvi[9]  = { 0, 1, 2, 1, 0, 2, 2, 0, 1 };
    const float* masks[3] = { l_mask, v_mask, a_mask };

    for (int off = 0; off < 9; off++) {
        const float* kv  = U[kvi[off]];
        const float* msk = masks[kvi[off]];
        const float* qin = U[qsrc[off]];
        float* qouts[2] = { pq0, pq1 };

        for (int j = 0; j < 2; j++) {
            int i = off * 2 + j;
            float* Sout = (j == 0) ? pS : pP;

            // scores (NT) + fused scale / residual / mask epilogue
            if (j == 0) {
                tc_gemm<1, true, false><<<dim3(SEQ / 64, SEQ / 128, BATCH * NH), 256>>>(
                    qin, nullptr, kv, nullptr, 0, Sout,
                    SEQ, SEQ, HD, DIM, DIM, SEQ,
                    NH,
                    (long)SEQ * DIM, (long)HD,
                    (long)SEQ * DIM, (long)HD,
                    (long)NH * SEQ * SEQ, (long)SEQ * SEQ,
                    nullptr, msk, cvec, i);
            } else {
                tc_gemm<2, true, false><<<dim3(SEQ / 64, SEQ / 128, BATCH * NH), 256>>>(
                    qin, nullptr, kv, nullptr, 0, Sout,
                    SEQ, SEQ, HD, DIM, DIM, SEQ,
                    NH,
                    (long)SEQ * DIM, (long)HD,
                    (long)SEQ * DIM, (long)HD,
                    (long)NH * SEQ * SEQ, (long)SEQ * SEQ,
                    pS, msk, cvec, i);
            }

            // softmax: layer0 S->P (keep S), layer1 in-place on P
            softmax_kernel<<<BATCH * NH * SEQ, 256>>>(Sout, pP);

            // ctx[b,q,h*64+d] = P[b,h] @ kv_head
            tc_gemm<0, false, false><<<dim3(HD / 64, SEQ / 128, BATCH * NH), 256>>>(
                pP, nullptr, kv, nullptr, 0, pctx,
                SEQ, HD, SEQ, SEQ, DIM, DIM,
                NH,
                (long)NH * SEQ * SEQ, (long)SEQ * SEQ,
                (long)SEQ * DIM, (long)HD,
                (long)SEQ * DIM, (long)HD,
                nullptr, nullptr, nullptr, 0);

            // tmp = qin @ minus_top[i] + ctx @ W[i]   (fused concat+proj)
            tc_gemm<0, false, true><<<dim3(DIM / 64, M / 128, 1), 256>>>(
                qin, pctx,
                minus_w + (long)i * 2 * DIM * DIM,       // top 512 rows
                pW + (long)i * DIM * DIM, DIM,           // B2 = W[i], Ksplit=512
                ptmp,
                M, DIM, 2 * DIM, DIM, DIM, DIM,
                1, 0, 0, 0, 0, 0, 0,
                nullptr, nullptr, nullptr, 0);

            // LN -> new q
            float* qout = qouts[j];
            ln_kernel<<<M, 256>>>(ptmp, qout, n2_g + (long)i * DIM, n2_b + (long)i * DIM);

            // pool into slot k
            int k = (off % 3) * 2 + j;
            pool_reduce<<<16, 256>>>(qout, psum + (long)k * 4096, pmax + (long)k * 4096);

            qin = qout;
        }
    }

    clf_kernel<<<BATCH * 9, 256>>>(psum, pmax, clf_w, out);
}

// round 6
// speedup vs baseline: 8.8624x; 1.9857x over previous
#include <cuda_runtime.h>
#include <math.h>

// ---------------------------------------------------------------------------
// Problem constants
// ---------------------------------------------------------------------------
#define BATCH 8
#define NH 8
#define SEQ 512
#define DIM 512
#define HD 64
#define USZ ((long)BATCH * SEQ * DIM)       // 2097152 floats per stream buffer

// ---------------------------------------------------------------------------
// Scratch (device globals; no allocations allowed)
// ---------------------------------------------------------------------------
__device__ float g_U[3 * 2097152];          // unified l,v,a
__device__ float g_qA[9 * 2097152];         // layer-0 outputs per stream
__device__ float g_qB[9 * 2097152];         // layer-1 outputs per stream
__device__ float g_ctx[9 * 2097152];
__device__ float g_tmp[9 * 2097152];
__device__ float g_S[9L * BATCH * NH * SEQ * SEQ];  // layer-0 scores (576MB)
__device__ float g_W[18 * DIM * DIM];       // proj @ minus_bottom
__device__ float g_sum[6 * BATCH * DIM];
__device__ float g_max[6 * BATCH * DIM];

// ---------------------------------------------------------------------------
// MMA / cp.async helpers
// ---------------------------------------------------------------------------
#define MMA_TF32(d, a, b)                                                     \
    asm volatile(                                                             \
        "mma.sync.aligned.m16n8k8.row.col.f32.tf32.tf32.f32 "                 \
        "{%0,%1,%2,%3},{%4,%5,%6,%7},{%8,%9},{%0,%1,%2,%3};"                  \
        : "+f"(d[0]), "+f"(d[1]), "+f"(d[2]), "+f"(d[3])                      \
        : "r"(a[0]), "r"(a[1]), "r"(a[2]), "r"(a[3]), "r"(b[0]), "r"(b[1]))

__device__ __forceinline__ void cp16(unsigned dst, const float* src)
{
    asm volatile("cp.async.cg.shared.global [%0], [%1], 16;"
                 :: "r"(dst), "l"(src));
}

// stream tables: qsrc[s] = s/3 ; kvi[s] via 2-bit packed code {0,1,2,1,0,2,2,0,1}
__device__ __forceinline__ int kvi_of(int s) { return (75876 >> (2 * s)) & 3; }

// ---------------------------------------------------------------------------
// Shared GEMM body (from verified round-5 tc_gemm, NN, plain epilogue).
// CTA tile 128x64x16, cp.async 3-stage. K%16==0, lda%4==0, 16B-aligned ptrs.
// SPLIT: for k >= Ksplit, read A2 / B2 (k rebased).
// ---------------------------------------------------------------------------
template<bool SPLIT>
__device__ __forceinline__ void gemm_body(
    const float* __restrict__ A, const float* __restrict__ A2,
    const float* __restrict__ B, const float* __restrict__ B2,
    int Ksplit, float* __restrict__ C,
    int K, int lda, int ldb, int ldc)
{
    __shared__ float As[3][128 * 20];
    __shared__ float Bs[3][1280];

    const int tid = threadIdx.x;
    const int bm = blockIdx.y * 128;
    const int bn = blockIdx.x * 64;
    const int warp = tid >> 5;
    const int warpm = warp & 3, warpn = warp >> 2;
    const int lane = tid & 31;
    const int lr = lane >> 2, lc = lane & 3;
    const int nT = K >> 4;

    const int ar = tid >> 2;
    const int aj = (tid & 3) << 2;
    const long aoff0 = (long)(bm + ar) * lda + aj;
    const long aoff1 = (long)(bm + ar + 64) * lda + aj;
    const long boffg = (long)(tid >> 4) * ldb + bn + ((tid & 15) << 2);

    const unsigned asb = (unsigned)__cvta_generic_to_shared(As);
    const unsigned bsb = (unsigned)__cvta_generic_to_shared(Bs);
    const unsigned sa0 = asb + (unsigned)(ar * 20 + aj) * 4u;
    const unsigned sa1 = asb + (unsigned)((ar + 64) * 20 + aj) * 4u;
    const unsigned sb0 = bsb + (unsigned)((tid >> 4) * 72 + ((tid & 15) << 2)) * 4u;

    auto load_tile = [&](int t, int st) {
        int k0 = t << 4;
        const float* Ab = A; const float* Bb = B; int kk = k0;
        if (SPLIT && k0 >= Ksplit) { Ab = A2; Bb = B2; kk = k0 - Ksplit; }
        unsigned oa = (unsigned)st * (128 * 20 * 4u);
        unsigned ob = (unsigned)st * (1280 * 4u);
        cp16(sa0 + oa, Ab + aoff0 + kk);
        cp16(sa1 + oa, Ab + aoff1 + kk);
        cp16(sb0 + ob, Bb + (long)kk * ldb + boffg);
    };

#pragma unroll
    for (int st = 0; st < 2; st++) {
        if (st < nT) load_tile(st, st);
        asm volatile("cp.async.commit_group;");
    }

    float acc[2][4][4] = {};
    const int afb = (warpm * 32 + lr) * 20 + lc;
    const int bfb = lc * 72 + warpn * 32 + lr;

    for (int t = 0; t < nT; t++) {
        asm volatile("cp.async.wait_group 1;");
        __syncthreads();
        if (t + 2 < nT) load_tile(t + 2, (t + 2) % 3);
        asm volatile("cp.async.commit_group;");

        const float* as = As[t % 3];
        const float* bs = Bs[t % 3];
#pragma unroll
        for (int ks = 0; ks < 2; ks++) {
            unsigned af[2][4];
#pragma unroll
            for (int mi = 0; mi < 2; mi++) {
                int base = afb + mi * 320 + ks * 8;
                af[mi][0] = __float_as_uint(as[base]);
                af[mi][1] = __float_as_uint(as[base + 160]);
                af[mi][2] = __float_as_uint(as[base + 4]);
                af[mi][3] = __float_as_uint(as[base + 164]);
            }
            unsigned bf[4][2];
#pragma unroll
            for (int ni = 0; ni < 4; ni++) {
                int base = bfb + ni * 8 + ks * 576;
                bf[ni][0] = __float_as_uint(bs[base]);
                bf[ni][1] = __float_as_uint(bs[base + 288]);
            }
#pragma unroll
            for (int mi = 0; mi < 2; mi++)
#pragma unroll
                for (int ni = 0; ni < 4; ni++)
                    MMA_TF32(acc[mi][ni], af[mi], bf[ni]);
        }
    }

#pragma unroll
    for (int mi = 0; mi < 2; mi++)
#pragma unroll
        for (int ni = 0; ni < 4; ni++) {
            int row0 = bm + warpm * 32 + mi * 16 + lr;
            int col = bn + warpn * 32 + ni * 8 + lc * 2;
#pragma unroll
            for (int rr = 0; rr < 2; rr++) {
                int row = row0 + rr * 8;
                *(float2*)&C[(long)row * ldc + col] =
                    make_float2(acc[mi][ni][rr * 2], acc[mi][ni][rr * 2 + 1]);
            }
        }
}

// plain batched wrapper (W precompute, unify l/v)
__global__ void __launch_bounds__(256) tc_plain(
    const float* __restrict__ A, const float* __restrict__ B,
    float* __restrict__ C, int K, int lda, int ldb, int ldc,
    long sA, long sB, long sC)
{
    int z = blockIdx.z;
    gemm_body<false>(A + z * sA, nullptr, B + z * sB, nullptr, 0,
                     C + z * sC, K, lda, ldb, ldc);
}

// batched minus GEMM: tmp[s] = qin[s] @ minus_top[i] + ctx[s] @ W[i], i=s*2+L
template<int LAYER>
__global__ void __launch_bounds__(256) minus_b(
    const float* __restrict__ Ub, const float* __restrict__ Qprev,
    const float* __restrict__ ctxb, const float* __restrict__ minus_w,
    const float* __restrict__ Wb, float* __restrict__ tmpb)
{
    int s = blockIdx.z;
    const float* A = (LAYER == 0) ? Ub + (s / 3) * USZ : Qprev + s * USZ;
    int i = s * 2 + LAYER;
    gemm_body<true>(A, ctxb + s * USZ,
                    minus_w + (long)i * 2 * DIM * DIM,
                    Wb + (long)i * DIM * DIM,
                    DIM, tmpb + s * USZ, 2 * DIM, DIM, DIM, DIM);
}

// ---------------------------------------------------------------------------
// Fused attention: scores + softmax + ctx for ALL streams in one launch.
// grid (16, 576): x = 32-row q-tile, y = z = s*64 + bb*8 + hh. 256 threads.
// Layer 0: writes post-mask scores S to gmem. Layer 1: reads S as residual.
// smem: Ks[512][68] + Qs[32][68] + Ps[32][516] + reductions  (~210 KB dyn).
// ---------------------------------------------------------------------------
template<int LAYER>
__global__ void __launch_bounds__(256, 1) attn_fused(
    const float* __restrict__ Ub, const float* __restrict__ Qprev,
    float* __restrict__ Sb, float* __restrict__ ctxb,
    const float* __restrict__ m0, const float* __restrict__ m1,
    const float* __restrict__ m2, const float* __restrict__ cvec)
{
    extern __shared__ float sm[];
    float* Ks   = sm;                  // 512*68
    float* Qs   = Ks + 512 * 68;       // 32*68
    float* Ps   = Qs + 32 * 68;        // 32*516
    float* red  = Ps + 32 * 516;       // 8*32
    float* rmax = red + 256;           // 32
    float* rinv = rmax + 32;           // 32

    const int z = blockIdx.y;
    const int s = z >> 6;
    const int bb = (z >> 3) & 7;
    const int hh = z & 7;
    const int row0 = blockIdx.x * 32;

    const int tid = threadIdx.x;
    const int w = tid >> 5;
    const int lane = tid & 31;
    const int lr = lane >> 2, lc = lane & 3;

    const int kv = kvi_of(s);
    const float* qin = (LAYER == 0) ? Ub + (s / 3) * USZ : Qprev + s * USZ;
    const float* kvp = Ub + kv * USZ;
    const float* maskp = ((kv == 0) ? m0 : (kv == 1) ? m1 : m2) + bb * SEQ;

    const float* Qg = qin + (long)bb * SEQ * DIM + (long)row0 * DIM + hh * HD;
    const float* Kg = kvp + (long)bb * SEQ * DIM + hh * HD;

    // ---- stage K (512x64) and Q (32x64) ----
    {
        unsigned ksb = (unsigned)__cvta_generic_to_shared(Ks);
        unsigned qsb = (unsigned)__cvta_generic_to_shared(Qs);
        int r = tid >> 4, c = (tid & 15) << 2;
#pragma unroll
        for (int i = 0; i < 32; i++) {
            int rr = r + i * 16;
            cp16(ksb + (unsigned)(rr * 68 + c) * 4u, Kg + (long)rr * DIM + c);
        }
#pragma unroll
        for (int i = 0; i < 2; i++) {
            int idx = tid + i * 256;
            int qr = idx >> 4, qc = (idx & 15) << 2;
            cp16(qsb + (unsigned)(qr * 68 + qc) * 4u, Qg + (long)qr * DIM + qc);
        }
        asm volatile("cp.async.commit_group;");
        asm volatile("cp.async.wait_group 0;");
    }
    __syncthreads();

    // ---- scores: warp w owns seq cols [w*64, w*64+64) ----
    float acc[2][8][4] = {};
    const int nbase = w * 64;
#pragma unroll
    for (int ks = 0; ks < 8; ks++) {
        unsigned af[2][4];
#pragma unroll
        for (int mi = 0; mi < 2; mi++) {
            const float* q = &Qs[(mi * 16 + lr) * 68 + ks * 8 + lc];
            af[mi][0] = __float_as_uint(q[0]);
            af[mi][1] = __float_as_uint(q[8 * 68]);
            af[mi][2] = __float_as_uint(q[4]);
            af[mi][3] = __float_as_uint(q[8 * 68 + 4]);
        }
#pragma unroll
        for (int ni = 0; ni < 8; ni++) {
            unsigned bf[2];
            const float* kp = &Ks[(nbase + ni * 8 + lr) * 68 + ks * 8 + lc];
            bf[0] = __float_as_uint(kp[0]);
            bf[1] = __float_as_uint(kp[4]);
#pragma unroll
            for (int mi = 0; mi < 2; mi++)
                MMA_TF32(acc[mi][ni], af[mi], bf);
        }
    }

    // ---- scale + mask (+ c*prev / store S) ----
    float cv = 0.f;
    if (LAYER == 1) cv = cvec[s * 2 + 1];
    float mpen[8][2];
#pragma unroll
    for (int ni = 0; ni < 8; ni++) {
        mpen[ni][0] = 1e8f * (1.f - maskp[nbase + ni * 8 + lc * 2]);
        mpen[ni][1] = 1e8f * (1.f - maskp[nbase + ni * 8 + lc * 2 + 1]);
    }
    float* Sz = Sb + (long)z * SEQ * SEQ;
#pragma unroll
    for (int mi = 0; mi < 2; mi++)
#pragma unroll
        for (int rr = 0; rr < 2; rr++) {
            int rg = row0 + mi * 16 + rr * 8 + lr;
#pragma unroll
            for (int ni = 0; ni < 8; ni++) {
                int cg = nbase + ni * 8 + lc * 2;
                float v0 = acc[mi][ni][rr * 2] * 0.125f - mpen[ni][0];
                float v1 = acc[mi][ni][rr * 2 + 1] * 0.125f - mpen[ni][1];
                if (LAYER == 1) {
                    float2 pv = *(const float2*)&Sz[(long)rg * SEQ + cg];
                    v0 += cv * pv.x; v1 += cv * pv.y;
                } else {
                    *(float2*)&Sz[(long)rg * SEQ + cg] = make_float2(v0, v1);
                }
                acc[mi][ni][rr * 2] = v0;
                acc[mi][ni][rr * 2 + 1] = v1;
            }
        }

    // ---- softmax: row max ----
    float lred[4];
#pragma unroll
    for (int i = 0; i < 4; i++) {
        int mi = i >> 1, rr = i & 1;
        float m = -INFINITY;
#pragma unroll
        for (int ni = 0; ni < 8; ni++)
            m = fmaxf(m, fmaxf(acc[mi][ni][rr * 2], acc[mi][ni][rr * 2 + 1]));
        m = fmaxf(m, __shfl_xor_sync(0xffffffffu, m, 1));
        m = fmaxf(m, __shfl_xor_sync(0xffffffffu, m, 2));
        lred[i] = m;
    }
    if (lc == 0)
#pragma unroll
        for (int i = 0; i < 4; i++)
            red[w * 32 + (i >> 1) * 16 + (i & 1) * 8 + lr] = lred[i];
    __syncthreads();
    if (tid < 32) {
        float m = red[tid];
#pragma unroll
        for (int ww = 1; ww < 8; ww++) m = fmaxf(m, red[ww * 32 + tid]);
        rmax[tid] = m;
    }
    __syncthreads();

    // ---- exp -> Ps (unnormalized), row sum ----
#pragma unroll
    for (int i = 0; i < 4; i++) {
        int mi = i >> 1, rr = i & 1;
        int row = mi * 16 + rr * 8 + lr;
        float rm = rmax[row];
        float* prow = &Ps[row * 516 + nbase + lc * 2];
        float sum = 0.f;
#pragma unroll
        for (int ni = 0; ni < 8; ni++) {
            float e0 = expf(acc[mi][ni][rr * 2] - rm);
            float e1 = expf(acc[mi][ni][rr * 2 + 1] - rm);
            prow[ni * 8] = e0; prow[ni * 8 + 1] = e1;
            sum += e0 + e1;
        }
        sum += __shfl_xor_sync(0xffffffffu, sum, 1);
        sum += __shfl_xor_sync(0xffffffffu, sum, 2);
        lred[i] = sum;
    }
    if (lc == 0)
#pragma unroll
        for (int i = 0; i < 4; i++)
            red[w * 32 + (i >> 1) * 16 + (i & 1) * 8 + lr] = lred[i];
    __syncthreads();
    if (tid < 32) {
        float sum = 0.f;
#pragma unroll
        for (int ww = 0; ww < 8; ww++) sum += red[ww * 32 + tid];
        rinv[tid] = 1.f / sum;
    }
    __syncthreads();

    // ---- ctx = Ps(32x512) @ Ks(512x64); warps split K-range ----
    float cacc[2][8][4] = {};
#pragma unroll
    for (int ks = 0; ks < 8; ks++) {
        int kg = w * 64 + ks * 8;
        unsigned af[2][4];
#pragma unroll
        for (int mi = 0; mi < 2; mi++) {
            const float* p = &Ps[(mi * 16 + lr) * 516 + kg + lc];
            af[mi][0] = __float_as_uint(p[0]);
            af[mi][1] = __float_as_uint(p[8 * 516]);
            af[mi][2] = __float_as_uint(p[4]);
            af[mi][3] = __float_as_uint(p[8 * 516 + 4]);
        }
#pragma unroll
        for (int ni = 0; ni < 8; ni++) {
            unsigned bf[2];
            const float* kp = &Ks[(kg + lc) * 68 + ni * 8 + lr];
            bf[0] = __float_as_uint(kp[0]);
            bf[1] = __float_as_uint(kp[4 * 68]);
#pragma unroll
            for (int mi = 0; mi < 2; mi++)
                MMA_TF32(cacc[mi][ni], af[mi], bf);
        }
    }
    __syncthreads();   // all mma reads of Ks/Ps done -> overlay partials on Ks
    {
        float* pb = Ks + w * (32 * 68);
#pragma unroll
        for (int mi = 0; mi < 2; mi++)
#pragma unroll
            for (int rr = 0; rr < 2; rr++) {
                int row = mi * 16 + rr * 8 + lr;
#pragma unroll
                for (int ni = 0; ni < 8; ni++)
                    *(float2*)&pb[row * 68 + ni * 8 + lc * 2] =
                        make_float2(cacc[mi][ni][rr * 2], cacc[mi][ni][rr * 2 + 1]);
            }
    }
    __syncthreads();
    float* ctxg = ctxb + (long)s * USZ + (long)bb * SEQ * DIM
                + (long)row0 * DIM + hh * HD;
#pragma unroll
    for (int i = 0; i < 8; i++) {
        int idx = tid + i * 256;
        int row = idx >> 6, col = idx & 63;
        float sum = 0.f;
#pragma unroll
        for (int ww = 0; ww < 8; ww++) sum += Ks[ww * 2176 + row * 68 + col];
        ctxg[(long)row * DIM + col] = sum * rinv[row];
    }
}

// ---------------------------------------------------------------------------
// Fallback TF32 GEMM (round-3 verified) — unify-a only (K=205 unaligned).
// ---------------------------------------------------------------------------
__device__ __forceinline__ float to_tf32(float x)
{
    unsigned u;
    asm("cvt.rna.tf32.f32 %0, %1;" : "=r"(u) : "f"(x));
    return __uint_as_float(u);
}

__global__ void __launch_bounds__(256) gen_gemm(
    const float* __restrict__ A, const float* __restrict__ B,
    float* __restrict__ C, int M, int N, int K, int lda, int ldb, int ldc)
{
    __shared__ float As[2][16][136];
    __shared__ float Bs[2][16][72];

    const int tid = threadIdx.x;
    const int bm = blockIdx.y * 128;
    const int bn = blockIdx.x * 64;
    const int warp = tid >> 5;
    const int warpm = warp & 3;
    const int warpn = warp >> 2;
    const int lane = tid & 31;
    const int lr = lane >> 2;
    const int lc = lane & 3;
    const int nTiles = (K + 15) >> 4;

    float acc[2][4][4] = {};

    auto loadTile = [&](int t, float* ra, float* rb) {
        int k0 = t << 4;
#pragma unroll
        for (int i = 0; i < 8; i++) {
            int idx = tid + i * 256;
            int m = idx >> 4, kk = idx & 15;
            int kg = k0 + kk;
            float v = (kg < K) ? A[(long)(bm + m) * lda + kg] : 0.f;
            ra[i] = to_tf32(v);
        }
#pragma unroll
        for (int i = 0; i < 4; i++) {
            int idx = tid + i * 256;
            int kk = idx >> 6, n = idx & 63;
            int kg = k0 + kk;
            float v = (kg < K) ? B[(long)kg * ldb + bn + n] : 0.f;
            rb[i] = to_tf32(v);
        }
    };
    auto storeTile = [&](int st, const float* ra, const float* rb) {
#pragma unroll
        for (int i = 0; i < 8; i++) {
            int idx = tid + i * 256;
            As[st][idx & 15][idx >> 4] = ra[i];
        }
#pragma unroll
        for (int i = 0; i < 4; i++) {
            int idx = tid + i * 256;
            Bs[st][idx >> 6][idx & 63] = rb[i];
        }
    };

    {
        float ra[8], rb[4];
        loadTile(0, ra, rb);
        storeTile(0, ra, rb);
    }
    __syncthreads();

    for (int t = 0; t < nTiles; t++) {
        const int cur = t & 1;
        const bool hasNext = (t + 1 < nTiles);
        float ra[8], rb[4];
        if (hasNext) loadTile(t + 1, ra, rb);

#pragma unroll
        for (int ks = 0; ks < 2; ks++) {
            const int kb = ks * 8;
            unsigned af[2][4];
#pragma unroll
            for (int mi = 0; mi < 2; mi++) {
                int mo = warpm * 32 + mi * 16 + lr;
                af[mi][0] = __float_as_uint(As[cur][kb + lc][mo]);
                af[mi][1] = __float_as_uint(As[cur][kb + lc][mo + 8]);
                af[mi][2] = __float_as_uint(As[cur][kb + lc + 4][mo]);
                af[mi][3] = __float_as_uint(As[cur][kb + lc + 4][mo + 8]);
            }
            unsigned bf[4][2];
#pragma unroll
            for (int ni = 0; ni < 4; ni++) {
                int no = warpn * 32 + ni * 8 + lr;
                bf[ni][0] = __float_as_uint(Bs[cur][kb + lc][no]);
                bf[ni][1] = __float_as_uint(Bs[cur][kb + lc + 4][no]);
            }
#pragma unroll
            for (int mi = 0; mi < 2; mi++)
#pragma unroll
                for (int ni = 0; ni < 4; ni++)
                    MMA_TF32(acc[mi][ni], af[mi], bf[ni]);
        }

        if (hasNext) storeTile((t + 1) & 1, ra, rb);
        __syncthreads();
    }

#pragma unroll
    for (int mi = 0; mi < 2; mi++)
#pragma unroll
        for (int ni = 0; ni < 4; ni++) {
            int row0 = bm + warpm * 32 + mi * 16 + lr;
            int col = bn + warpn * 32 + ni * 8 + lc * 2;
#pragma unroll
            for (int rr = 0; rr < 2; rr++) {
                int row = row0 + rr * 8;
                C[(long)row * ldc + col] = acc[mi][ni][rr * 2 + 0];
                C[(long)row * ldc + col + 1] = acc[mi][ni][rr * 2 + 1];
            }
        }
}

// ---------------------------------------------------------------------------
// LayerNorm (warp-shuffle reductions). pstride selects per-stream params:
// param offset = (row >> 12) * pstride.
// ---------------------------------------------------------------------------
__global__ void __launch_bounds__(256) ln_all(
    const float* __restrict__ X, float* __restrict__ Y,
    const float* __restrict__ g, const float* __restrict__ b, int pstride)
{
    long row = blockIdx.x;
    int pi = (int)(row >> 12);
    g += (long)pi * pstride;
    b += (long)pi * pstride;
    const float* x = X + row * DIM;
    float* y = Y + row * DIM;
    int tid = threadIdx.x;
    float v0 = x[tid], v1 = x[tid + 256];

    __shared__ float ws[8];
    __shared__ float bc[2];

    float sum = v0 + v1;
#pragma unroll
    for (int o = 16; o > 0; o >>= 1) sum += __shfl_xor_sync(0xffffffffu, sum, o);
    if ((tid & 31) == 0) ws[tid >> 5] = sum;
    __syncthreads();
    if (tid == 0) {
        float t = 0.f;
#pragma unroll
        for (int i = 0; i < 8; i++) t += ws[i];
        bc[0] = t * (1.f / DIM);
    }
    __syncthreads();
    float mu = bc[0];

    float d0 = v0 - mu, d1 = v1 - mu;
    float q = d0 * d0 + d1 * d1;
#pragma unroll
    for (int o = 16; o > 0; o >>= 1) q += __shfl_xor_sync(0xffffffffu, q, o);
    if ((tid & 31) == 0) ws[tid >> 5] = q;
    __syncthreads();
    if (tid == 0) {
        float t = 0.f;
#pragma unroll
        for (int i = 0; i < 8; i++) t += ws[i];
        bc[1] = rsqrtf(t * (1.f / DIM) + 1e-5f);
    }
    __syncthreads();
    float rstd = bc[1];

    y[tid] = d0 * rstd * g[tid] + b[tid];
    y[tid + 256] = d1 * rstd * g[tid + 256] + b[tid + 256];
}

// ---------------------------------------------------------------------------
// Pooling
// ---------------------------------------------------------------------------
__global__ void pool_init(float* s, float* m, int n)
{
    int i = blockIdx.x * blockDim.x + threadIdx.x;
    if (i < n) { s[i] = 0.f; m[i] = -INFINITY; }
}

__device__ __forceinline__ void atomicMaxF(float* addr, float val)
{
    int old = __float_as_int(*addr);
    while (__int_as_float(old) < val) {
        int assumed = old;
        old = atomicCAS((int*)addr, assumed, __float_as_int(val));
        if (old == assumed) break;
    }
}

// grid (16, 3 slots, 4 row-chunks); slot g <- streams {g, g+3, g+6}
__global__ void __launch_bounds__(256) pool_b(
    const float* __restrict__ Qb, float* __restrict__ sum,
    float* __restrict__ mx, int layer)
{
    int idx = blockIdx.x * 256 + threadIdx.x;   // (b,d)
    int bb = idx >> 9, d = idx & 511;
    int g = blockIdx.y;
    int r0 = blockIdx.z * 128;
    float s = 0.f, m = -INFINITY;
#pragma unroll
    for (int t = 0; t < 3; t++) {
        const float* p = Qb + (long)(g + t * 3) * USZ
                       + (long)bb * SEQ * DIM + (long)r0 * DIM + d;
        for (int r = 0; r < 128; r++) {
            float v = p[(long)r * DIM];
            s += v;
            m = fmaxf(m, v);
        }
    }
    int k = g * 2 + layer;
    atomicAdd(&sum[k * 4096 + idx], s);
    atomicMaxF(&mx[k * 4096 + idx], m);
}

// ---------------------------------------------------------------------------
// Classifier
// ---------------------------------------------------------------------------
__global__ void __launch_bounds__(256) clf_kernel(
    const float* __restrict__ sum, const float* __restrict__ mx,
    const float* __restrict__ W, float* __restrict__ out)
{
    int bb = blockIdx.x / 9, cls = blockIdx.x % 9;
    int tid = threadIdx.x;
    float acc = 0.f;
    for (int j = tid; j < 3072; j += 256) {
        int k = j >> 9, d = j & 511;
        float sm = sum[k * 4096 + bb * 512 + d] * (1.f / 1536.f);
        float mv = mx[k * 4096 + bb * 512 + d];
        acc += sm * W[(long)j * 9 + cls] + mv * W[(long)(3072 + j) * 9 + cls];
    }
    __shared__ float red[256];
    red[tid] = acc;
    __syncthreads();
    for (int s = 128; s > 0; s >>= 1) {
        if (tid < s) red[tid] += red[tid + s];
        __syncthreads();
    }
    if (tid == 0) out[bb * 9 + cls] = red[0];
}

// ---------------------------------------------------------------------------
// Host orchestration
// ---------------------------------------------------------------------------
extern "C" void kernel_launch(void* const* d_in, const int* in_sizes, int n_in,
                              void* d_out, int out_size)
{
    const float* l      = (const float*)d_in[0];
    const float* v      = (const float*)d_in[1];
    const float* a      = (const float*)d_in[2];
    const float* l_mask = (const float*)d_in[3];
    const float* v_mask = (const float*)d_in[4];
    const float* a_mask = (const float*)d_in[5];
    const float* wl     = (const float*)d_in[6];
    const float* wv     = (const float*)d_in[7];
    const float* wa     = (const float*)d_in[8];
    const float* n1_g   = (const float*)d_in[9];
    const float* n1_b   = (const float*)d_in[10];
    const float* proj_w = (const float*)d_in[11];
    const float* minus_w= (const float*)d_in[12];
    const float* n2_g   = (const float*)d_in[13];
    const float* n2_b   = (const float*)d_in[14];
    const float* cvec   = (const float*)d_in[15];
    const float* clf_w  = (const float*)d_in[16];
    float* out          = (float*)d_out;

    float *pU, *pqA, *pqB, *pctx, *ptmp, *pS, *pW, *psum, *pmax;
    cudaGetSymbolAddress((void**)&pU, g_U);
    cudaGetSymbolAddress((void**)&pqA, g_qA);
    cudaGetSymbolAddress((void**)&pqB, g_qB);
    cudaGetSymbolAddress((void**)&pctx, g_ctx);
    cudaGetSymbolAddress((void**)&ptmp, g_tmp);
    cudaGetSymbolAddress((void**)&pS, g_S);
    cudaGetSymbolAddress((void**)&pW, g_W);
    cudaGetSymbolAddress((void**)&psum, g_sum);
    cudaGetSymbolAddress((void**)&pmax, g_max);

    const int SMEM_ATTN = (512 * 68 + 32 * 68 + 32 * 516 + 256 + 64) * 4;
    cudaFuncSetAttribute(attn_fused<0>,
        cudaFuncAttributeMaxDynamicSharedMemorySize, SMEM_ATTN);
    cudaFuncSetAttribute(attn_fused<1>,
        cudaFuncAttributeMaxDynamicSharedMemorySize, SMEM_ATTN);

    pool_init<<<96, 256>>>(psum, pmax, 6 * BATCH * DIM);

    // W[i] = proj_w[i] @ minus_w[i][512:1024]  (batched over 18 blocks)
    tc_plain<<<dim3(8, 4, 18), 256>>>(
        proj_w, minus_w + (long)DIM * DIM, pW, DIM, DIM, DIM, DIM,
        (long)DIM * DIM, (long)2 * DIM * DIM, (long)DIM * DIM);

    // --- Unify + LN ---
    tc_plain<<<dim3(8, 32, 1), 256>>>(l, wl, ptmp, 768, 768, DIM, DIM, 0, 0, 0);
    ln_all<<<4096, 256>>>(ptmp, pU + 0 * USZ, n1_g, n1_b, 0);
    tc_plain<<<dim3(8, 32, 1), 256>>>(v, wv, ptmp, 640, 640, DIM, DIM, 0, 0, 0);
    ln_all<<<4096, 256>>>(ptmp, pU + 1 * USZ, n1_g, n1_b, 0);
    gen_gemm<<<dim3(8, 32), 256>>>(a, wa, ptmp, 4096, DIM, 205, 205, DIM, DIM);
    ln_all<<<4096, 256>>>(ptmp, pU + 2 * USZ, n1_g, n1_b, 0);

    // --- layer 0 (all 9 streams batched) ---
    attn_fused<0><<<dim3(16, 576), 256, SMEM_ATTN>>>(
        pU, nullptr, pS, pctx, l_mask, v_mask, a_mask, cvec);
    minus_b<0><<<dim3(8, 32, 9), 256>>>(pU, nullptr, pctx, minus_w, pW, ptmp);
    ln_all<<<9 * 4096, 256>>>(ptmp, pqA, n2_g, n2_b, 2 * DIM);
    pool_b<<<dim3(16, 3, 4), 256>>>(pqA, psum, pmax, 0);

    // --- layer 1 ---
    attn_fused<1><<<dim3(16, 576), 256, SMEM_ATTN>>>(
        pU, pqA, pS, pctx, l_mask, v_mask, a_mask, cvec);
    minus_b<1><<<dim3(8, 32, 9), 256>>>(pU, pqA, pctx, minus_w, pW, ptmp);
    ln_all<<<9 * 4096, 256>>>(ptmp, pqB, n2_g + DIM, n2_b + DIM, 2 * DIM);
    pool_b<<<dim3(16, 3, 4), 256>>>(pqB, psum, pmax, 1);

    clf_kernel<<<BATCH * 9, 256>>>(psum, pmax, clf_w, out);
}

// round 7
// speedup vs baseline: 10.3837x; 1.1717x over previous
#include <cuda_runtime.h>
#include <math.h>

// ---------------------------------------------------------------------------
// Problem constants
// ---------------------------------------------------------------------------
#define BATCH 8
#define NH 8
#define SEQ 512
#define DIM 512
#define HD 64
#define USZ ((long)BATCH * SEQ * DIM)       // 2097152 floats per stream buffer

// ---------------------------------------------------------------------------
// Scratch (device globals; no allocations allowed)
// ---------------------------------------------------------------------------
__device__ float g_U[3 * 2097152];          // unified l,v,a
__device__ float g_qA[9 * 2097152];         // layer-0 outputs per stream
__device__ float g_qB[9 * 2097152];         // layer-1 outputs per stream
__device__ float g_ctx[9 * 2097152];
__device__ float g_tmp[9 * 2097152];
__device__ float g_W[18 * DIM * DIM];       // proj @ minus_bottom
__device__ float g_sum[6 * BATCH * DIM];
__device__ float g_max[6 * BATCH * DIM];

// ---------------------------------------------------------------------------
// MMA / cp.async helpers
// ---------------------------------------------------------------------------
#define MMA_TF32(d, a, b)                                                     \
    asm volatile(                                                             \
        "mma.sync.aligned.m16n8k8.row.col.f32.tf32.tf32.f32 "                 \
        "{%0,%1,%2,%3},{%4,%5,%6,%7},{%8,%9},{%0,%1,%2,%3};"                  \
        : "+f"(d[0]), "+f"(d[1]), "+f"(d[2]), "+f"(d[3])                      \
        : "r"(a[0]), "r"(a[1]), "r"(a[2]), "r"(a[3]), "r"(b[0]), "r"(b[1]))

__device__ __forceinline__ void cp16(unsigned dst, const float* src)
{
    asm volatile("cp.async.cg.shared.global [%0], [%1], 16;"
                 :: "r"(dst), "l"(src));
}

// stream tables: qsrc[s] = s/3 ; kvi[s] via 2-bit packed code {0,1,2,1,0,2,2,0,1}
__device__ __forceinline__ int kvi_of(int s) { return (75876 >> (2 * s)) & 3; }

// ---------------------------------------------------------------------------
// Shared GEMM body (verified): NN, CTA tile 128x64x16, cp.async 3-stage.
// K%16==0, lda%4==0, 16B-aligned ptrs. SPLIT: k >= Ksplit reads A2/B2.
// ---------------------------------------------------------------------------
template<bool SPLIT>
__device__ __forceinline__ void gemm_body(
    const float* __restrict__ A, const float* __restrict__ A2,
    const float* __restrict__ B, const float* __restrict__ B2,
    int Ksplit, float* __restrict__ C,
    int K, int lda, int ldb, int ldc)
{
    __shared__ float As[3][128 * 20];
    __shared__ float Bs[3][1280];

    const int tid = threadIdx.x;
    const int bm = blockIdx.y * 128;
    const int bn = blockIdx.x * 64;
    const int warp = tid >> 5;
    const int warpm = warp & 3, warpn = warp >> 2;
    const int lane = tid & 31;
    const int lr = lane >> 2, lc = lane & 3;
    const int nT = K >> 4;

    const int ar = tid >> 2;
    const int aj = (tid & 3) << 2;
    const long aoff0 = (long)(bm + ar) * lda + aj;
    const long aoff1 = (long)(bm + ar + 64) * lda + aj;
    const long boffg = (long)(tid >> 4) * ldb + bn + ((tid & 15) << 2);

    const unsigned asb = (unsigned)__cvta_generic_to_shared(As);
    const unsigned bsb = (unsigned)__cvta_generic_to_shared(Bs);
    const unsigned sa0 = asb + (unsigned)(ar * 20 + aj) * 4u;
    const unsigned sa1 = asb + (unsigned)((ar + 64) * 20 + aj) * 4u;
    const unsigned sb0 = bsb + (unsigned)((tid >> 4) * 72 + ((tid & 15) << 2)) * 4u;

    auto load_tile = [&](int t, int st) {
        int k0 = t << 4;
        const float* Ab = A; const float* Bb = B; int kk = k0;
        if (SPLIT && k0 >= Ksplit) { Ab = A2; Bb = B2; kk = k0 - Ksplit; }
        unsigned oa = (unsigned)st * (128 * 20 * 4u);
        unsigned ob = (unsigned)st * (1280 * 4u);
        cp16(sa0 + oa, Ab + aoff0 + kk);
        cp16(sa1 + oa, Ab + aoff1 + kk);
        cp16(sb0 + ob, Bb + (long)kk * ldb + boffg);
    };

#pragma unroll
    for (int st = 0; st < 2; st++) {
        if (st < nT) load_tile(st, st);
        asm volatile("cp.async.commit_group;");
    }

    float acc[2][4][4] = {};
    const int afb = (warpm * 32 + lr) * 20 + lc;
    const int bfb = lc * 72 + warpn * 32 + lr;

    for (int t = 0; t < nT; t++) {
        asm volatile("cp.async.wait_group 1;");
        __syncthreads();
        if (t + 2 < nT) load_tile(t + 2, (t + 2) % 3);
        asm volatile("cp.async.commit_group;");

        const float* as = As[t % 3];
        const float* bs = Bs[t % 3];
#pragma unroll
        for (int ks = 0; ks < 2; ks++) {
            unsigned af[2][4];
#pragma unroll
            for (int mi = 0; mi < 2; mi++) {
                int base = afb + mi * 320 + ks * 8;
                af[mi][0] = __float_as_uint(as[base]);
                af[mi][1] = __float_as_uint(as[base + 160]);
                af[mi][2] = __float_as_uint(as[base + 4]);
                af[mi][3] = __float_as_uint(as[base + 164]);
            }
            unsigned bf[4][2];
#pragma unroll
            for (int ni = 0; ni < 4; ni++) {
                int base = bfb + ni * 8 + ks * 576;
                bf[ni][0] = __float_as_uint(bs[base]);
                bf[ni][1] = __float_as_uint(bs[base + 288]);
            }
#pragma unroll
            for (int mi = 0; mi < 2; mi++)
#pragma unroll
                for (int ni = 0; ni < 4; ni++)
                    MMA_TF32(acc[mi][ni], af[mi], bf[ni]);
        }
    }

#pragma unroll
    for (int mi = 0; mi < 2; mi++)
#pragma unroll
        for (int ni = 0; ni < 4; ni++) {
            int row0 = bm + warpm * 32 + mi * 16 + lr;
            int col = bn + warpn * 32 + ni * 8 + lc * 2;
#pragma unroll
            for (int rr = 0; rr < 2; rr++) {
                int row = row0 + rr * 8;
                *(float2*)&C[(long)row * ldc + col] =
                    make_float2(acc[mi][ni][rr * 2], acc[mi][ni][rr * 2 + 1]);
            }
        }
}

// plain batched wrapper (W precompute, unify l/v)
__global__ void __launch_bounds__(256) tc_plain(
    const float* __restrict__ A, const float* __restrict__ B,
    float* __restrict__ C, int K, int lda, int ldb, int ldc,
    long sA, long sB, long sC)
{
    int z = blockIdx.z;
    gemm_body<false>(A + z * sA, nullptr, B + z * sB, nullptr, 0,
                     C + z * sC, K, lda, ldb, ldc);
}

// batched minus GEMM: tmp[s] = qin[s] @ minus_top[i] + ctx[s] @ W[i], i=s*2+L
template<int LAYER>
__global__ void __launch_bounds__(256) minus_b(
    const float* __restrict__ Ub, const float* __restrict__ Qprev,
    const float* __restrict__ ctxb, const float* __restrict__ minus_w,
    const float* __restrict__ Wb, float* __restrict__ tmpb)
{
    int s = blockIdx.z;
    const float* A = (LAYER == 0) ? Ub + (s / 3) * USZ : Qprev + s * USZ;
    int i = s * 2 + LAYER;
    gemm_body<true>(A, ctxb + s * USZ,
                    minus_w + (long)i * 2 * DIM * DIM,
                    Wb + (long)i * DIM * DIM,
                    DIM, tmpb + s * USZ, 2 * DIM, DIM, DIM, DIM);
}

// ---------------------------------------------------------------------------
// Persistent-K fused attention: one CTA per z = s*64 + bb*8 + hh (grid 576).
// K (512x64) stays resident in smem; loop over 16 q-tiles of 32 rows.
// No score buffer: layer 1 uses Qeff = Q1 + c*Q0 and penalty scale (1+c),
// algebraically identical to c * (masked layer-0 scores) residual.
// smem: Ks[512][68] + Qs[32][68] + Ps[32][516] + red/rmax/rinv  (~210 KB).
// ---------------------------------------------------------------------------
template<int LAYER>
__global__ void __launch_bounds__(256, 1) attn_fused(
    const float* __restrict__ Ub, const float* __restrict__ Qprev,
    float* __restrict__ ctxb,
    const float* __restrict__ m0, const float* __restrict__ m1,
    const float* __restrict__ m2, const float* __restrict__ cvec)
{
    extern __shared__ float sm[];
    float* Ks   = sm;                  // 512*68
    float* Qs   = Ks + 512 * 68;       // 32*68
    float* Ps   = Qs + 32 * 68;        // 32*516
    float* red  = Ps + 32 * 516;       // 8*32
    float* rmax = red + 256;           // 32
    float* rinv = rmax + 32;           // 32

    const int z = blockIdx.x;
    const int s = z >> 6;
    const int bb = (z >> 3) & 7;
    const int hh = z & 7;

    const int tid = threadIdx.x;
    const int w = tid >> 5;
    const int lane = tid & 31;
    const int lr = lane >> 2, lc = lane & 3;

    const int kv = kvi_of(s);
    const float* q0p = Ub + (s / 3) * USZ;
    const float* qin = (LAYER == 0) ? q0p : Qprev + s * USZ;
    const float* kvp = Ub + kv * USZ;
    const float* maskp = ((kv == 0) ? m0 : (kv == 1) ? m1 : m2) + bb * SEQ;

    const float* Qg  = qin + (long)bb * SEQ * DIM + hh * HD;
    const float* Q0g = q0p + (long)bb * SEQ * DIM + hh * HD;
    const float* Kg  = kvp + (long)bb * SEQ * DIM + hh * HD;

    float cv = 0.f, pscale = 1e8f;
    if (LAYER == 1) { cv = cvec[s * 2 + 1]; pscale = (1.f + cv) * 1e8f; }

    // ---- stage K (512x64), resident for whole CTA ----
    {
        unsigned ksb = (unsigned)__cvta_generic_to_shared(Ks);
        int r = tid >> 4, c = (tid & 15) << 2;
#pragma unroll
        for (int i = 0; i < 32; i++) {
            int rr = r + i * 16;
            cp16(ksb + (unsigned)(rr * 68 + c) * 4u, Kg + (long)rr * DIM + c);
        }
        asm volatile("cp.async.commit_group;");
        asm volatile("cp.async.wait_group 0;");
    }
    __syncthreads();

    // mask penalties for this warp's score columns (reused across q-tiles)
    const int nbase = w * 64;
    float mpen[8][2];
#pragma unroll
    for (int ni = 0; ni < 8; ni++) {
        mpen[ni][0] = pscale * (1.f - maskp[nbase + ni * 8 + lc * 2]);
        mpen[ni][1] = pscale * (1.f - maskp[nbase + ni * 8 + lc * 2 + 1]);
    }

    for (int qt = 0; qt < 16; qt++) {
        const int row0 = qt * 32;

        // ---- stage Q tile (32x64); layer 1 stages Qeff = Q1 + c*Q0 ----
        if (LAYER == 0) {
            unsigned qsb = (unsigned)__cvta_generic_to_shared(Qs);
#pragma unroll
            for (int i = 0; i < 2; i++) {
                int idx = tid + i * 256;
                int qr = idx >> 4, qc = (idx & 15) << 2;
                cp16(qsb + (unsigned)(qr * 68 + qc) * 4u,
                     Qg + (long)(row0 + qr) * DIM + qc);
            }
            asm volatile("cp.async.commit_group;");
            asm volatile("cp.async.wait_group 0;");
        } else {
#pragma unroll
            for (int i = 0; i < 8; i++) {
                int idx = tid + i * 256;
                int qr = idx >> 6, qc = idx & 63;
                long go = (long)(row0 + qr) * DIM + qc;
                Qs[qr * 68 + qc] = Qg[go] + cv * Q0g[go];
            }
        }
        __syncthreads();   // Qs ready; also fences prev iteration's Ps/rinv use

        // ---- scores: warp w owns seq cols [w*64, w*64+64) ----
        float acc[2][8][4] = {};
#pragma unroll
        for (int ks = 0; ks < 8; ks++) {
            unsigned af[2][4];
#pragma unroll
            for (int mi = 0; mi < 2; mi++) {
                const float* q = &Qs[(mi * 16 + lr) * 68 + ks * 8 + lc];
                af[mi][0] = __float_as_uint(q[0]);
                af[mi][1] = __float_as_uint(q[8 * 68]);
                af[mi][2] = __float_as_uint(q[4]);
                af[mi][3] = __float_as_uint(q[8 * 68 + 4]);
            }
#pragma unroll
            for (int ni = 0; ni < 8; ni++) {
                unsigned bf[2];
                const float* kp = &Ks[(nbase + ni * 8 + lr) * 68 + ks * 8 + lc];
                bf[0] = __float_as_uint(kp[0]);
                bf[1] = __float_as_uint(kp[4]);
#pragma unroll
                for (int mi = 0; mi < 2; mi++)
                    MMA_TF32(acc[mi][ni], af[mi], bf);
            }
        }

        // ---- scale + mask ----
#pragma unroll
        for (int mi = 0; mi < 2; mi++)
#pragma unroll
            for (int ni = 0; ni < 8; ni++) {
                acc[mi][ni][0] = acc[mi][ni][0] * 0.125f - mpen[ni][0];
                acc[mi][ni][1] = acc[mi][ni][1] * 0.125f - mpen[ni][1];
                acc[mi][ni][2] = acc[mi][ni][2] * 0.125f - mpen[ni][0];
                acc[mi][ni][3] = acc[mi][ni][3] * 0.125f - mpen[ni][1];
            }

        // ---- softmax: row max ----
        float lred[4];
#pragma unroll
        for (int i = 0; i < 4; i++) {
            int mi = i >> 1, rr = i & 1;
            float m = -INFINITY;
#pragma unroll
            for (int ni = 0; ni < 8; ni++)
                m = fmaxf(m, fmaxf(acc[mi][ni][rr * 2], acc[mi][ni][rr * 2 + 1]));
            m = fmaxf(m, __shfl_xor_sync(0xffffffffu, m, 1));
            m = fmaxf(m, __shfl_xor_sync(0xffffffffu, m, 2));
            lred[i] = m;
        }
        if (lc == 0)
#pragma unroll
            for (int i = 0; i < 4; i++)
                red[w * 32 + (i >> 1) * 16 + (i & 1) * 8 + lr] = lred[i];
        __syncthreads();
        if (tid < 32) {
            float m = red[tid];
#pragma unroll
            for (int ww = 1; ww < 8; ww++) m = fmaxf(m, red[ww * 32 + tid]);
            rmax[tid] = m;
        }
        __syncthreads();

        // ---- exp -> Ps (unnormalized), row sum ----
#pragma unroll
        for (int i = 0; i < 4; i++) {
            int mi = i >> 1, rr = i & 1;
            int row = mi * 16 + rr * 8 + lr;
            float rm = rmax[row];
            float* prow = &Ps[row * 516 + nbase + lc * 2];
            float sum = 0.f;
#pragma unroll
            for (int ni = 0; ni < 8; ni++) {
                float e0 = expf(acc[mi][ni][rr * 2] - rm);
                float e1 = expf(acc[mi][ni][rr * 2 + 1] - rm);
                prow[ni * 8] = e0; prow[ni * 8 + 1] = e1;
                sum += e0 + e1;
            }
            sum += __shfl_xor_sync(0xffffffffu, sum, 1);
            sum += __shfl_xor_sync(0xffffffffu, sum, 2);
            lred[i] = sum;
        }
        if (lc == 0)
#pragma unroll
            for (int i = 0; i < 4; i++)
                red[w * 32 + (i >> 1) * 16 + (i & 1) * 8 + lr] = lred[i];
        __syncthreads();
        if (tid < 32) {
            float sum = 0.f;
#pragma unroll
            for (int ww = 0; ww < 8; ww++) sum += red[ww * 32 + tid];
            rinv[tid] = 1.f / sum;
        }
        __syncthreads();

        // ---- ctx = Ps(32x512) @ Ks(512x64); warp w owns out cols [w*8,w*8+8) ----
        float cacc[2][4] = {};
#pragma unroll 8
        for (int ks = 0; ks < 64; ks++) {
            int kg = ks * 8;
            unsigned af[2][4];
#pragma unroll
            for (int mi = 0; mi < 2; mi++) {
                const float* p = &Ps[(mi * 16 + lr) * 516 + kg + lc];
                af[mi][0] = __float_as_uint(p[0]);
                af[mi][1] = __float_as_uint(p[8 * 516]);
                af[mi][2] = __float_as_uint(p[4]);
                af[mi][3] = __float_as_uint(p[8 * 516 + 4]);
            }
            unsigned bf[2];
            bf[0] = __float_as_uint(Ks[(kg + lc) * 68 + w * 8 + lr]);
            bf[1] = __float_as_uint(Ks[(kg + lc + 4) * 68 + w * 8 + lr]);
#pragma unroll
            for (int mi = 0; mi < 2; mi++)
                MMA_TF32(cacc[mi], af[mi], bf);
        }

        float* ctxg = ctxb + (long)s * USZ + (long)bb * SEQ * DIM
                    + (long)row0 * DIM + hh * HD;
#pragma unroll
        for (int mi = 0; mi < 2; mi++)
#pragma unroll
            for (int rr = 0; rr < 2; rr++) {
                int row = mi * 16 + rr * 8 + lr;
                float inv = rinv[row];
                *(float2*)&ctxg[(long)row * DIM + w * 8 + lc * 2] =
                    make_float2(cacc[mi][rr * 2] * inv, cacc[mi][rr * 2 + 1] * inv);
            }
        // next iteration's staging __syncthreads() orders Ps/rinv reuse
    }
}

// ---------------------------------------------------------------------------
// Fallback TF32 GEMM (round-3 verified) — unify-a only (K=205 unaligned).
// ---------------------------------------------------------------------------
__device__ __forceinline__ float to_tf32(float x)
{
    unsigned u;
    asm("cvt.rna.tf32.f32 %0, %1;" : "=r"(u) : "f"(x));
    return __uint_as_float(u);
}

__global__ void __launch_bounds__(256) gen_gemm(
    const float* __restrict__ A, const float* __restrict__ B,
    float* __restrict__ C, int M, int N, int K, int lda, int ldb, int ldc)
{
    __shared__ float As[2][16][136];
    __shared__ float Bs[2][16][72];

    const int tid = threadIdx.x;
    const int bm = blockIdx.y * 128;
    const int bn = blockIdx.x * 64;
    const int warp = tid >> 5;
    const int warpm = warp & 3;
    const int warpn = warp >> 2;
    const int lane = tid & 31;
    const int lr = lane >> 2;
    const int lc = lane & 3;
    const int nTiles = (K + 15) >> 4;

    float acc[2][4][4] = {};

    auto loadTile = [&](int t, float* ra, float* rb) {
        int k0 = t << 4;
#pragma unroll
        for (int i = 0; i < 8; i++) {
            int idx = tid + i * 256;
            int m = idx >> 4, kk = idx & 15;
            int kg = k0 + kk;
            float v = (kg < K) ? A[(long)(bm + m) * lda + kg] : 0.f;
            ra[i] = to_tf32(v);
        }
#pragma unroll
        for (int i = 0; i < 4; i++) {
            int idx = tid + i * 256;
            int kk = idx >> 6, n = idx & 63;
            int kg = k0 + kk;
            float v = (kg < K) ? B[(long)kg * ldb + bn + n] : 0.f;
            rb[i] = to_tf32(v);
        }
    };
    auto storeTile = [&](int st, const float* ra, const float* rb) {
#pragma unroll
        for (int i = 0; i < 8; i++) {
            int idx = tid + i * 256;
            As[st][idx & 15][idx >> 4] = ra[i];
        }
#pragma unroll
        for (int i = 0; i < 4; i++) {
            int idx = tid + i * 256;
            Bs[st][idx >> 6][idx & 63] = rb[i];
        }
    };

    {
        float ra[8], rb[4];
        loadTile(0, ra, rb);
        storeTile(0, ra, rb);
    }
    __syncthreads();

    for (int t = 0; t < nTiles; t++) {
        const int cur = t & 1;
        const bool hasNext = (t + 1 < nTiles);
        float ra[8], rb[4];
        if (hasNext) loadTile(t + 1, ra, rb);

#pragma unroll
        for (int ks = 0; ks < 2; ks++) {
            const int kb = ks * 8;
            unsigned af[2][4];
#pragma unroll
            for (int mi = 0; mi < 2; mi++) {
                int mo = warpm * 32 + mi * 16 + lr;
                af[mi][0] = __float_as_uint(As[cur][kb + lc][mo]);
                af[mi][1] = __float_as_uint(As[cur][kb + lc][mo + 8]);
                af[mi][2] = __float_as_uint(As[cur][kb + lc + 4][mo]);
                af[mi][3] = __float_as_uint(As[cur][kb + lc + 4][mo + 8]);
            }
            unsigned bf[4][2];
#pragma unroll
            for (int ni = 0; ni < 4; ni++) {
                int no = warpn * 32 + ni * 8 + lr;
                bf[ni][0] = __float_as_uint(Bs[cur][kb + lc][no]);
                bf[ni][1] = __float_as_uint(Bs[cur][kb + lc + 4][no]);
            }
#pragma unroll
            for (int mi = 0; mi < 2; mi++)
#pragma unroll
                for (int ni = 0; ni < 4; ni++)
                    MMA_TF32(acc[mi][ni], af[mi], bf[ni]);
        }

        if (hasNext) storeTile((t + 1) & 1, ra, rb);
        __syncthreads();
    }

#pragma unroll
    for (int mi = 0; mi < 2; mi++)
#pragma unroll
        for (int ni = 0; ni < 4; ni++) {
            int row0 = bm + warpm * 32 + mi * 16 + lr;
            int col = bn + warpn * 32 + ni * 8 + lc * 2;
#pragma unroll
            for (int rr = 0; rr < 2; rr++) {
                int row = row0 + rr * 8;
                C[(long)row * ldc + col] = acc[mi][ni][rr * 2 + 0];
                C[(long)row * ldc + col + 1] = acc[mi][ni][rr * 2 + 1];
            }
        }
}

// ---------------------------------------------------------------------------
// LayerNorm (warp-shuffle reductions). param offset = (row >> 12) * pstride.
// ---------------------------------------------------------------------------
__global__ void __launch_bounds__(256) ln_all(
    const float* __restrict__ X, float* __restrict__ Y,
    const float* __restrict__ g, const float* __restrict__ b, int pstride)
{
    long row = blockIdx.x;
    int pi = (int)(row >> 12);
    g += (long)pi * pstride;
    b += (long)pi * pstride;
    const float* x = X + row * DIM;
    float* y = Y + row * DIM;
    int tid = threadIdx.x;
    float v0 = x[tid], v1 = x[tid + 256];

    __shared__ float ws[8];
    __shared__ float bc[2];

    float sum = v0 + v1;
#pragma unroll
    for (int o = 16; o > 0; o >>= 1) sum += __shfl_xor_sync(0xffffffffu, sum, o);
    if ((tid & 31) == 0) ws[tid >> 5] = sum;
    __syncthreads();
    if (tid == 0) {
        float t = 0.f;
#pragma unroll
        for (int i = 0; i < 8; i++) t += ws[i];
        bc[0] = t * (1.f / DIM);
    }
    __syncthreads();
    float mu = bc[0];

    float d0 = v0 - mu, d1 = v1 - mu;
    float q = d0 * d0 + d1 * d1;
#pragma unroll
    for (int o = 16; o > 0; o >>= 1) q += __shfl_xor_sync(0xffffffffu, q, o);
    if ((tid & 31) == 0) ws[tid >> 5] = q;
    __syncthreads();
    if (tid == 0) {
        float t = 0.f;
#pragma unroll
        for (int i = 0; i < 8; i++) t += ws[i];
        bc[1] = rsqrtf(t * (1.f / DIM) + 1e-5f);
    }
    __syncthreads();
    float rstd = bc[1];

    y[tid] = d0 * rstd * g[tid] + b[tid];
    y[tid + 256] = d1 * rstd * g[tid + 256] + b[tid + 256];
}

// ---------------------------------------------------------------------------
// Pooling
// ---------------------------------------------------------------------------
__global__ void pool_init(float* s, float* m, int n)
{
    int i = blockIdx.x * blockDim.x + threadIdx.x;
    if (i < n) { s[i] = 0.f; m[i] = -INFINITY; }
}

__device__ __forceinline__ void atomicMaxF(float* addr, float val)
{
    int old = __float_as_int(*addr);
    while (__int_as_float(old) < val) {
        int assumed = old;
        old = atomicCAS((int*)addr, assumed, __float_as_int(val));
        if (old == assumed) break;
    }
}

// grid (16, 3 slots, 4 row-chunks); slot g <- streams {g, g+3, g+6}
__global__ void __launch_bounds__(256) pool_b(
    const float* __restrict__ Qb, float* __restrict__ sum,
    float* __restrict__ mx, int layer)
{
    int idx = blockIdx.x * 256 + threadIdx.x;   // (b,d)
    int bb = idx >> 9, d = idx & 511;
    int g = blockIdx.y;
    int r0 = blockIdx.z * 128;
    float s = 0.f, m = -INFINITY;
#pragma unroll
    for (int t = 0; t < 3; t++) {
        const float* p = Qb + (long)(g + t * 3) * USZ
                       + (long)bb * SEQ * DIM + (long)r0 * DIM + d;
        for (int r = 0; r < 128; r++) {
            float v = p[(long)r * DIM];
            s += v;
            m = fmaxf(m, v);
        }
    }
    int k = g * 2 + layer;
    atomicAdd(&sum[k * 4096 + idx], s);
    atomicMaxF(&mx[k * 4096 + idx], m);
}

// ---------------------------------------------------------------------------
// Classifier
// ---------------------------------------------------------------------------
__global__ void __launch_bounds__(256) clf_kernel(
    const float* __restrict__ sum, const float* __restrict__ mx,
    const float* __restrict__ W, float* __restrict__ out)
{
    int bb = blockIdx.x / 9, cls = blockIdx.x % 9;
    int tid = threadIdx.x;
    float acc = 0.f;
    for (int j = tid; j < 3072; j += 256) {
        int k = j >> 9, d = j & 511;
        float sm = sum[k * 4096 + bb * 512 + d] * (1.f / 1536.f);
        float mv = mx[k * 4096 + bb * 512 + d];
        acc += sm * W[(long)j * 9 + cls] + mv * W[(long)(3072 + j) * 9 + cls];
    }
    __shared__ float red[256];
    red[tid] = acc;
    __syncthreads();
    for (int s = 128; s > 0; s >>= 1) {
        if (tid < s) red[tid] += red[tid + s];
        __syncthreads();
    }
    if (tid == 0) out[bb * 9 + cls] = red[0];
}

// ---------------------------------------------------------------------------
// Host orchestration
// ---------------------------------------------------------------------------
extern "C" void kernel_launch(void* const* d_in, const int* in_sizes, int n_in,
                              void* d_out, int out_size)
{
    const float* l      = (const float*)d_in[0];
    const float* v      = (const float*)d_in[1];
    const float* a      = (const float*)d_in[2];
    const float* l_mask = (const float*)d_in[3];
    const float* v_mask = (const float*)d_in[4];
    const float* a_mask = (const float*)d_in[5];
    const float* wl     = (const float*)d_in[6];
    const float* wv     = (const float*)d_in[7];
    const float* wa     = (const float*)d_in[8];
    const float* n1_g   = (const float*)d_in[9];
    const float* n1_b   = (const float*)d_in[10];
    const float* proj_w = (const float*)d_in[11];
    const float* minus_w= (const float*)d_in[12];
    const float* n2_g   = (const float*)d_in[13];
    const float* n2_b   = (const float*)d_in[14];
    const float* cvec   = (const float*)d_in[15];
    const float* clf_w  = (const float*)d_in[16];
    float* out          = (float*)d_out;

    float *pU, *pqA, *pqB, *pctx, *ptmp, *pW, *psum, *pmax;
    cudaGetSymbolAddress((void**)&pU, g_U);
    cudaGetSymbolAddress((void**)&pqA, g_qA);
    cudaGetSymbolAddress((void**)&pqB, g_qB);
    cudaGetSymbolAddress((void**)&pctx, g_ctx);
    cudaGetSymbolAddress((void**)&ptmp, g_tmp);
    cudaGetSymbolAddress((void**)&pW, g_W);
    cudaGetSymbolAddress((void**)&psum, g_sum);
    cudaGetSymbolAddress((void**)&pmax, g_max);

    const int SMEM_ATTN = (512 * 68 + 32 * 68 + 32 * 516 + 256 + 64) * 4;
    cudaFuncSetAttribute(attn_fused<0>,
        cudaFuncAttributeMaxDynamicSharedMemorySize, SMEM_ATTN);
    cudaFuncSetAttribute(attn_fused<1>,
        cudaFuncAttributeMaxDynamicSharedMemorySize, SMEM_ATTN);

    pool_init<<<96, 256>>>(psum, pmax, 6 * BATCH * DIM);

    // W[i] = proj_w[i] @ minus_w[i][512:1024]  (batched over 18 blocks)
    tc_plain<<<dim3(8, 4, 18), 256>>>(
        proj_w, minus_w + (long)DIM * DIM, pW, DIM, DIM, DIM, DIM,
        (long)DIM * DIM, (long)2 * DIM * DIM, (long)DIM * DIM);

    // --- Unify + LN ---
    tc_plain<<<dim3(8, 32, 1), 256>>>(l, wl, ptmp, 768, 768, DIM, DIM, 0, 0, 0);
    ln_all<<<4096, 256>>>(ptmp, pU + 0 * USZ, n1_g, n1_b, 0);
    tc_plain<<<dim3(8, 32, 1), 256>>>(v, wv, ptmp, 640, 640, DIM, DIM, 0, 0, 0);
    ln_all<<<4096, 256>>>(ptmp, pU + 1 * USZ, n1_g, n1_b, 0);
    gen_gemm<<<dim3(8, 32), 256>>>(a, wa, ptmp, 4096, DIM, 205, 205, DIM, DIM);
    ln_all<<<4096, 256>>>(ptmp, pU + 2 * USZ, n1_g, n1_b, 0);

    // --- layer 0 (all 9 streams batched) ---
    attn_fused<0><<<576, 256, SMEM_ATTN>>>(
        pU, nullptr, pctx, l_mask, v_mask, a_mask, cvec);
    minus_b<0><<<dim3(8, 32, 9), 256>>>(pU, nullptr, pctx, minus_w, pW, ptmp);
    ln_all<<<9 * 4096, 256>>>(ptmp, pqA, n2_g, n2_b, 2 * DIM);
    pool_b<<<dim3(16, 3, 4), 256>>>(pqA, psum, pmax, 0);

    // --- layer 1 ---
    attn_fused<1><<<576, 256, SMEM_ATTN>>>(
        pU, pqA, pctx, l_mask, v_mask, a_mask, cvec);
    minus_b<1><<<dim3(8, 32, 9), 256>>>(pU, pqA, pctx, minus_w, pW, ptmp);
    ln_all<<<9 * 4096, 256>>>(ptmp, pqB, n2_g + DIM, n2_b + DIM, 2 * DIM);
    pool_b<<<dim3(16, 3, 4), 256>>>(pqB, psum, pmax, 1);

    clf_kernel<<<BATCH * 9, 256>>>(psum, pmax, clf_w, out);
}

// round 9
// speedup vs baseline: 11.6968x; 1.1265x over previous
#include <cuda_runtime.h>
#include <math.h>

// ---------------------------------------------------------------------------
// Problem constants
// ---------------------------------------------------------------------------
#define BATCH 8
#define NH 8
#define SEQ 512
#define DIM 512
#define HD 64
#define USZ ((long)BATCH * SEQ * DIM)       // 2097152 floats per stream buffer

// ---------------------------------------------------------------------------
// Scratch (device globals; no allocations allowed)
// ---------------------------------------------------------------------------
__device__ float g_U[3 * 2097152];          // unified l,v,a
__device__ float g_qA[9 * 2097152];         // layer-0 outputs per stream
__device__ float g_qB[9 * 2097152];         // layer-1 outputs per stream
__device__ float g_ctx[9 * 2097152];
__device__ float g_tmp[9 * 2097152];
__device__ float g_W[18 * DIM * DIM];       // proj @ minus_bottom
__device__ float g_sum[6 * BATCH * DIM];
__device__ float g_max[6 * BATCH * DIM];

// ---------------------------------------------------------------------------
// MMA / cp.async helpers
// ---------------------------------------------------------------------------
#define MMA_TF32(d, a, b)                                                     \
    asm volatile(                                                             \
        "mma.sync.aligned.m16n8k8.row.col.f32.tf32.tf32.f32 "                 \
        "{%0,%1,%2,%3},{%4,%5,%6,%7},{%8,%9},{%0,%1,%2,%3};"                  \
        : "+f"(d[0]), "+f"(d[1]), "+f"(d[2]), "+f"(d[3])                      \
        : "r"(a[0]), "r"(a[1]), "r"(a[2]), "r"(a[3]), "r"(b[0]), "r"(b[1]))

__device__ __forceinline__ void cp16(unsigned dst, const float* src)
{
    asm volatile("cp.async.cg.shared.global [%0], [%1], 16;"
                 :: "r"(dst), "l"(src));
}

// stream tables: qsrc[s] = s/3 ; kvi[s] via 2-bit packed code {0,1,2,1,0,2,2,0,1}
__device__ __forceinline__ int kvi_of(int s) { return (75876 >> (2 * s)) & 3; }

// ---------------------------------------------------------------------------
// Shared GEMM body (verified): NN, CTA tile 128x64x16, cp.async 3-stage.
// K%16==0, lda%4==0, 16B-aligned ptrs. SPLIT: k >= Ksplit reads A2/B2.
// ---------------------------------------------------------------------------
template<bool SPLIT>
__device__ __forceinline__ void gemm_body(
    const float* __restrict__ A, const float* __restrict__ A2,
    const float* __restrict__ B, const float* __restrict__ B2,
    int Ksplit, float* __restrict__ C,
    int K, int lda, int ldb, int ldc)
{
    __shared__ float As[3][128 * 20];
    __shared__ float Bs[3][1280];

    const int tid = threadIdx.x;
    const int bm = blockIdx.y * 128;
    const int bn = blockIdx.x * 64;
    const int warp = tid >> 5;
    const int warpm = warp & 3, warpn = warp >> 2;
    const int lane = tid & 31;
    const int lr = lane >> 2, lc = lane & 3;
    const int nT = K >> 4;

    const int ar = tid >> 2;
    const int aj = (tid & 3) << 2;
    const long aoff0 = (long)(bm + ar) * lda + aj;
    const long aoff1 = (long)(bm + ar + 64) * lda + aj;
    const long boffg = (long)(tid >> 4) * ldb + bn + ((tid & 15) << 2);

    const unsigned asb = (unsigned)__cvta_generic_to_shared(As);
    const unsigned bsb = (unsigned)__cvta_generic_to_shared(Bs);
    const unsigned sa0 = asb + (unsigned)(ar * 20 + aj) * 4u;
    const unsigned sa1 = asb + (unsigned)((ar + 64) * 20 + aj) * 4u;
    const unsigned sb0 = bsb + (unsigned)((tid >> 4) * 72 + ((tid & 15) << 2)) * 4u;

    auto load_tile = [&](int t, int st) {
        int k0 = t << 4;
        const float* Ab = A; const float* Bb = B; int kk = k0;
        if (SPLIT && k0 >= Ksplit) { Ab = A2; Bb = B2; kk = k0 - Ksplit; }
        unsigned oa = (unsigned)st * (128 * 20 * 4u);
        unsigned ob = (unsigned)st * (1280 * 4u);
        cp16(sa0 + oa, Ab + aoff0 + kk);
        cp16(sa1 + oa, Ab + aoff1 + kk);
        cp16(sb0 + ob, Bb + (long)kk * ldb + boffg);
    };

#pragma unroll
    for (int st = 0; st < 2; st++) {
        if (st < nT) load_tile(st, st);
        asm volatile("cp.async.commit_group;");
    }

    float acc[2][4][4] = {};
    const int afb = (warpm * 32 + lr) * 20 + lc;
    const int bfb = lc * 72 + warpn * 32 + lr;

    for (int t = 0; t < nT; t++) {
        asm volatile("cp.async.wait_group 1;");
        __syncthreads();
        if (t + 2 < nT) load_tile(t + 2, (t + 2) % 3);
        asm volatile("cp.async.commit_group;");

        const float* as = As[t % 3];
        const float* bs = Bs[t % 3];
#pragma unroll
        for (int ks = 0; ks < 2; ks++) {
            unsigned af[2][4];
#pragma unroll
            for (int mi = 0; mi < 2; mi++) {
                int base = afb + mi * 320 + ks * 8;
                af[mi][0] = __float_as_uint(as[base]);
                af[mi][1] = __float_as_uint(as[base + 160]);
                af[mi][2] = __float_as_uint(as[base + 4]);
                af[mi][3] = __float_as_uint(as[base + 164]);
            }
            unsigned bf[4][2];
#pragma unroll
            for (int ni = 0; ni < 4; ni++) {
                int base = bfb + ni * 8 + ks * 576;
                bf[ni][0] = __float_as_uint(bs[base]);
                bf[ni][1] = __float_as_uint(bs[base + 288]);
            }
#pragma unroll
            for (int mi = 0; mi < 2; mi++)
#pragma unroll
                for (int ni = 0; ni < 4; ni++)
                    MMA_TF32(acc[mi][ni], af[mi], bf[ni]);
        }
    }

#pragma unroll
    for (int mi = 0; mi < 2; mi++)
#pragma unroll
        for (int ni = 0; ni < 4; ni++) {
            int row0 = bm + warpm * 32 + mi * 16 + lr;
            int col = bn + warpn * 32 + ni * 8 + lc * 2;
#pragma unroll
            for (int rr = 0; rr < 2; rr++) {
                int row = row0 + rr * 8;
                *(float2*)&C[(long)row * ldc + col] =
                    make_float2(acc[mi][ni][rr * 2], acc[mi][ni][rr * 2 + 1]);
            }
        }
}

// plain batched wrapper (W precompute, unify l/v)
__global__ void __launch_bounds__(256) tc_plain(
    const float* __restrict__ A, const float* __restrict__ B,
    float* __restrict__ C, int K, int lda, int ldb, int ldc,
    long sA, long sB, long sC)
{
    int z = blockIdx.z;
    gemm_body<false>(A + z * sA, nullptr, B + z * sB, nullptr, 0,
                     C + z * sC, K, lda, ldb, ldc);
}

// batched minus GEMM: tmp[s] = qin[s] @ minus_top[i] + ctx[s] @ W[i], i=s*2+L
template<int LAYER>
__global__ void __launch_bounds__(256) minus_b(
    const float* __restrict__ Ub, const float* __restrict__ Qprev,
    const float* __restrict__ ctxb, const float* __restrict__ minus_w,
    const float* __restrict__ Wb, float* __restrict__ tmpb)
{
    int s = blockIdx.z;
    const float* A = (LAYER == 0) ? Ub + (s / 3) * USZ : Qprev + s * USZ;
    int i = s * 2 + LAYER;
    gemm_body<true>(A, ctxb + s * USZ,
                    minus_w + (long)i * 2 * DIM * DIM,
                    Wb + (long)i * DIM * DIM,
                    DIM, tmpb + s * USZ, 2 * DIM, DIM, DIM, DIM);
}

// ---------------------------------------------------------------------------
// Persistent-K fused attention: one CTA per z = s*64 + bb*8 + hh (grid 576).
// K (512x64) resident in smem; 16 q-tiles of 32 rows. Layer 1 uses
// Qeff = Q1 + c*Q0 and penalty scale (1+c). Softmax in log2 domain (exp2f).
// ctx: warp w takes k-slice [w*64,w*64+64) x all 64 cols; partials overlaid
// on Ps with per-row rotation swizzle (conflict-free), reduced with 1/rowsum.
// ---------------------------------------------------------------------------
#define L2E 1.44269504f

template<int LAYER>
__global__ void __launch_bounds__(256, 1) attn_fused(
    const float* __restrict__ Ub, const float* __restrict__ Qprev,
    float* __restrict__ ctxb,
    const float* __restrict__ m0, const float* __restrict__ m1,
    const float* __restrict__ m2, const float* __restrict__ cvec)
{
    extern __shared__ float sm[];
    float* Ks   = sm;                  // 512*68
    float* Qs   = Ks + 512 * 68;       // 32*68
    float* Ps   = Qs + 32 * 68;        // 32*516 (also ctx partial buffer 8*2048)
    float* red  = Ps + 32 * 516;       // 8*32
    float* rmax = red + 256;           // 32
    float* rinv = rmax + 32;           // 32

    const int z = blockIdx.x;
    const int s = z >> 6;
    const int bb = (z >> 3) & 7;
    const int hh = z & 7;

    const int tid = threadIdx.x;
    const int w = tid >> 5;
    const int lane = tid & 31;
    const int lr = lane >> 2, lc = lane & 3;

    const int kv = kvi_of(s);
    const float* q0p = Ub + (s / 3) * USZ;
    const float* qin = (LAYER == 0) ? q0p : Qprev + s * USZ;
    const float* kvp = Ub + kv * USZ;
    const float* maskp = ((kv == 0) ? m0 : (kv == 1) ? m1 : m2) + bb * SEQ;

    const float* Qg  = qin + (long)bb * SEQ * DIM + hh * HD;
    const float* Q0g = q0p + (long)bb * SEQ * DIM + hh * HD;
    const float* Kg  = kvp + (long)bb * SEQ * DIM + hh * HD;

    const float SCL = 0.125f * L2E;    // scores scale in log2 domain
    float cv = 0.f, pscale = 1e8f * L2E;
    if (LAYER == 1) { cv = cvec[s * 2 + 1]; pscale = (1.f + cv) * 1e8f * L2E; }

    // ---- stage K (512x64), resident for whole CTA ----
    {
        unsigned ksb = (unsigned)__cvta_generic_to_shared(Ks);
        int r = tid >> 4, c = (tid & 15) << 2;
#pragma unroll
        for (int i = 0; i < 32; i++) {
            int rr = r + i * 16;
            cp16(ksb + (unsigned)(rr * 68 + c) * 4u, Kg + (long)rr * DIM + c);
        }
        asm volatile("cp.async.commit_group;");
        asm volatile("cp.async.wait_group 0;");
    }
    __syncthreads();

    // mask penalties for this warp's score columns (reused across q-tiles)
    const int nbase = w * 64;
    float mpen[8][2];
#pragma unroll
    for (int ni = 0; ni < 8; ni++) {
        mpen[ni][0] = pscale * (1.f - maskp[nbase + ni * 8 + lc * 2]);
        mpen[ni][1] = pscale * (1.f - maskp[nbase + ni * 8 + lc * 2 + 1]);
    }

    for (int qt = 0; qt < 16; qt++) {
        const int row0 = qt * 32;

        // ---- stage Q tile (32x64); layer 1 stages Qeff = Q1 + c*Q0 ----
        if (LAYER == 0) {
            unsigned qsb = (unsigned)__cvta_generic_to_shared(Qs);
#pragma unroll
            for (int i = 0; i < 2; i++) {
                int idx = tid + i * 256;
                int qr = idx >> 4, qc = (idx & 15) << 2;
                cp16(qsb + (unsigned)(qr * 68 + qc) * 4u,
                     Qg + (long)(row0 + qr) * DIM + qc);
            }
            asm volatile("cp.async.commit_group;");
            asm volatile("cp.async.wait_group 0;");
        } else {
#pragma unroll
            for (int i = 0; i < 8; i++) {
                int idx = tid + i * 256;
                int qr = idx >> 6, qc = idx & 63;
                long go = (long)(row0 + qr) * DIM + qc;
                Qs[qr * 68 + qc] = Qg[go] + cv * Q0g[go];
            }
        }
        __syncthreads();   // Qs ready; fences prev iteration's Ps/rinv reads

        // ---- scores: warp w owns seq cols [w*64, w*64+64) ----
        float acc[2][8][4] = {};
#pragma unroll
        for (int ks = 0; ks < 8; ks++) {
            unsigned af[2][4];
#pragma unroll
            for (int mi = 0; mi < 2; mi++) {
                const float* q = &Qs[(mi * 16 + lr) * 68 + ks * 8 + lc];
                af[mi][0] = __float_as_uint(q[0]);
                af[mi][1] = __float_as_uint(q[8 * 68]);
                af[mi][2] = __float_as_uint(q[4]);
                af[mi][3] = __float_as_uint(q[8 * 68 + 4]);
            }
#pragma unroll
            for (int ni = 0; ni < 8; ni++) {
                unsigned bf[2];
                const float* kp = &Ks[(nbase + ni * 8 + lr) * 68 + ks * 8 + lc];
                bf[0] = __float_as_uint(kp[0]);
                bf[1] = __float_as_uint(kp[4]);
#pragma unroll
                for (int mi = 0; mi < 2; mi++)
                    MMA_TF32(acc[mi][ni], af[mi], bf);
            }
        }

        // ---- scale (log2 domain) + mask ----
#pragma unroll
        for (int mi = 0; mi < 2; mi++)
#pragma unroll
            for (int ni = 0; ni < 8; ni++) {
                acc[mi][ni][0] = acc[mi][ni][0] * SCL - mpen[ni][0];
                acc[mi][ni][1] = acc[mi][ni][1] * SCL - mpen[ni][1];
                acc[mi][ni][2] = acc[mi][ni][2] * SCL - mpen[ni][0];
                acc[mi][ni][3] = acc[mi][ni][3] * SCL - mpen[ni][1];
            }

        // ---- softmax: row max ----
        float lred[4];
#pragma unroll
        for (int i = 0; i < 4; i++) {
            int mi = i >> 1, rr = i & 1;
            float m = -INFINITY;
#pragma unroll
            for (int ni = 0; ni < 8; ni++)
                m = fmaxf(m, fmaxf(acc[mi][ni][rr * 2], acc[mi][ni][rr * 2 + 1]));
            m = fmaxf(m, __shfl_xor_sync(0xffffffffu, m, 1));
            m = fmaxf(m, __shfl_xor_sync(0xffffffffu, m, 2));
            lred[i] = m;
        }
        if (lc == 0)
#pragma unroll
            for (int i = 0; i < 4; i++)
                red[w * 32 + (i >> 1) * 16 + (i & 1) * 8 + lr] = lred[i];
        __syncthreads();
        if (tid < 32) {
            float m = red[tid];
#pragma unroll
            for (int ww = 1; ww < 8; ww++) m = fmaxf(m, red[ww * 32 + tid]);
            rmax[tid] = m;
        }
        __syncthreads();

        // ---- exp2 -> Ps (unnormalized), row sum ----
#pragma unroll
        for (int i = 0; i < 4; i++) {
            int mi = i >> 1, rr = i & 1;
            int row = mi * 16 + rr * 8 + lr;
            float rm = rmax[row];
            float* prow = &Ps[row * 516 + nbase + lc * 2];
            float sum = 0.f;
#pragma unroll
            for (int ni = 0; ni < 8; ni++) {
                float e0 = exp2f(acc[mi][ni][rr * 2] - rm);
                float e1 = exp2f(acc[mi][ni][rr * 2 + 1] - rm);
                prow[ni * 8] = e0; prow[ni * 8 + 1] = e1;
                sum += e0 + e1;
            }
            sum += __shfl_xor_sync(0xffffffffu, sum, 1);
            sum += __shfl_xor_sync(0xffffffffu, sum, 2);
            lred[i] = sum;
        }
        if (lc == 0)
#pragma unroll
            for (int i = 0; i < 4; i++)
                red[w * 32 + (i >> 1) * 16 + (i & 1) * 8 + lr] = lred[i];
        __syncthreads();
        if (tid < 32) {
            float sum = 0.f;
#pragma unroll
            for (int ww = 0; ww < 8; ww++) sum += red[ww * 32 + tid];
            rinv[tid] = 1.f / sum;
        }
        __syncthreads();

        // ---- ctx partials: warp w takes k-slice [w*64,w*64+64), all 64 cols
        float cacc[2][8][4] = {};
#pragma unroll
        for (int ks = 0; ks < 8; ks++) {
            const int kg = w * 64 + ks * 8;
            unsigned af[2][4];
#pragma unroll
            for (int mi = 0; mi < 2; mi++) {
                const float* p = &Ps[(mi * 16 + lr) * 516 + kg + lc];
                af[mi][0] = __float_as_uint(p[0]);
                af[mi][1] = __float_as_uint(p[8 * 516]);
                af[mi][2] = __float_as_uint(p[4]);
                af[mi][3] = __float_as_uint(p[8 * 516 + 4]);
            }
#pragma unroll
            for (int ni = 0; ni < 8; ni++) {
                unsigned bf[2];
                const float* kp = &Ks[(kg + lc) * 68 + ni * 8 + lr];
                bf[0] = __float_as_uint(kp[0]);
                bf[1] = __float_as_uint(kp[4 * 68]);
#pragma unroll
                for (int mi = 0; mi < 2; mi++)
                    MMA_TF32(cacc[mi][ni], af[mi], bf);
            }
        }
        __syncthreads();   // all Ps reads complete before overlay

        // store partials into Ps region, per-row rotated units (no conflicts)
        {
            float* pb = Ps + w * 2048;
#pragma unroll
            for (int mi = 0; mi < 2; mi++)
#pragma unroll
                for (int rr = 0; rr < 2; rr++) {
                    int row = mi * 16 + rr * 8 + lr;
#pragma unroll
                    for (int ni = 0; ni < 8; ni++) {
                        int u = (ni * 4 + lc + row * 4) & 31;
                        *(float2*)&pb[row * 64 + u * 2] =
                            make_float2(cacc[mi][ni][rr * 2],
                                        cacc[mi][ni][rr * 2 + 1]);
                    }
                }
        }
        __syncthreads();

        // reduce 8 partials, scale by rinv, store ctx (coalesced float2)
        float* ctxg = ctxb + (long)s * USZ + (long)bb * SEQ * DIM
                    + (long)row0 * DIM + hh * HD;
#pragma unroll
        for (int i = 0; i < 4; i++) {
            int idx = tid + i * 256;       // float2 unit over 32x32 units
            int row = idx >> 5;
            int u = idx & 31;
            int up = (u + row * 4) & 31;
            float sx = 0.f, sy = 0.f;
#pragma unroll
            for (int ww = 0; ww < 8; ww++) {
                float2 vv = *(float2*)&Ps[ww * 2048 + row * 64 + up * 2];
                sx += vv.x; sy += vv.y;
            }
            float inv = rinv[row];
            *(float2*)&ctxg[(long)row * DIM + u * 2] =
                make_float2(sx * inv, sy * inv);
        }
        // next iteration's first __syncthreads orders Ps reuse
    }
}

// ---------------------------------------------------------------------------
// Fallback TF32 GEMM (round-3 verified) — unify-a only (K=205 unaligned).
// ---------------------------------------------------------------------------
__device__ __forceinline__ float to_tf32(float x)
{
    unsigned u;
    asm("cvt.rna.tf32.f32 %0, %1;" : "=r"(u) : "f"(x));
    return __uint_as_float(u);
}

__global__ void __launch_bounds__(256) gen_gemm(
    const float* __restrict__ A, const float* __restrict__ B,
    float* __restrict__ C, int M, int N, int K, int lda, int ldb, int ldc)
{
    __shared__ float As[2][16][136];
    __shared__ float Bs[2][16][72];

    const int tid = threadIdx.x;
    const int bm = blockIdx.y * 128;
    const int bn = blockIdx.x * 64;
    const int warp = tid >> 5;
    const int warpm = warp & 3;
    const int warpn = warp >> 2;
    const int lane = tid & 31;
    const int lr = lane >> 2;
    const int lc = lane & 3;
    const int nTiles = (K + 15) >> 4;

    float acc[2][4][4] = {};

    auto loadTile = [&](int t, float* ra, float* rb) {
        int k0 = t << 4;
#pragma unroll
        for (int i = 0; i < 8; i++) {
            int idx = tid + i * 256;
            int m = idx >> 4, kk = idx & 15;
            int kg = k0 + kk;
            float v = (kg < K) ? A[(long)(bm + m) * lda + kg] : 0.f;
            ra[i] = to_tf32(v);
        }
#pragma unroll
        for (int i = 0; i < 4; i++) {
            int idx = tid + i * 256;
            int kk = idx >> 6, n = idx & 63;
            int kg = k0 + kk;
            float v = (kg < K) ? B[(long)kg * ldb + bn + n] : 0.f;
            rb[i] = to_tf32(v);
        }
    };
    auto storeTile = [&](int st, const float* ra, const float* rb) {
#pragma unroll
        for (int i = 0; i < 8; i++) {
            int idx = tid + i * 256;
            As[st][idx & 15][idx >> 4] = ra[i];
        }
#pragma unroll
        for (int i = 0; i < 4; i++) {
            int idx = tid + i * 256;
            Bs[st][idx >> 6][idx & 63] = rb[i];
        }
    };

    {
        float ra[8], rb[4];
        loadTile(0, ra, rb);
        storeTile(0, ra, rb);
    }
    __syncthreads();

    for (int t = 0; t < nTiles; t++) {
        const int cur = t & 1;
        const bool hasNext = (t + 1 < nTiles);
        float ra[8], rb[4];
        if (hasNext) loadTile(t + 1, ra, rb);

#pragma unroll
        for (int ks = 0; ks < 2; ks++) {
            const int kb = ks * 8;
            unsigned af[2][4];
#pragma unroll
            for (int mi = 0; mi < 2; mi++) {
                int mo = warpm * 32 + mi * 16 + lr;
                af[mi][0] = __float_as_uint(As[cur][kb + lc][mo]);
                af[mi][1] = __float_as_uint(As[cur][kb + lc][mo + 8]);
                af[mi][2] = __float_as_uint(As[cur][kb + lc + 4][mo]);
                af[mi][3] = __float_as_uint(As[cur][kb + lc + 4][mo + 8]);
            }
            unsigned bf[4][2];
#pragma unroll
            for (int ni = 0; ni < 4; ni++) {
                int no = warpn * 32 + ni * 8 + lr;
                bf[ni][0] = __float_as_uint(Bs[cur][kb + lc][no]);
                bf[ni][1] = __float_as_uint(Bs[cur][kb + lc + 4][no]);
            }
#pragma unroll
            for (int mi = 0; mi < 2; mi++)
#pragma unroll
                for (int ni = 0; ni < 4; ni++)
                    MMA_TF32(acc[mi][ni], af[mi], bf[ni]);
        }

        if (hasNext) storeTile((t + 1) & 1, ra, rb);
        __syncthreads();
    }

#pragma unroll
    for (int mi = 0; mi < 2; mi++)
#pragma unroll
        for (int ni = 0; ni < 4; ni++) {
            int row0 = bm + warpm * 32 + mi * 16 + lr;
            int col = bn + warpn * 32 + ni * 8 + lc * 2;
#pragma unroll
            for (int rr = 0; rr < 2; rr++) {
                int row = row0 + rr * 8;
                C[(long)row * ldc + col] = acc[mi][ni][rr * 2 + 0];
                C[(long)row * ldc + col + 1] = acc[mi][ni][rr * 2 + 1];
            }
        }
}

// ---------------------------------------------------------------------------
// LayerNorm (warp-shuffle reductions). param offset = (row >> 12) * pstride.
// ---------------------------------------------------------------------------
__global__ void __launch_bounds__(256) ln_all(
    const float* __restrict__ X, float* __restrict__ Y,
    const float* __restrict__ g, const float* __restrict__ b, int pstride)
{
    long row = blockIdx.x;
    int pi = (int)(row >> 12);
    g += (long)pi * pstride;
    b += (long)pi * pstride;
    const float* x = X + row * DIM;
    float* y = Y + row * DIM;
    int tid = threadIdx.x;
    float v0 = x[tid], v1 = x[tid + 256];

    __shared__ float ws[8];
    __shared__ float bc[2];

    float sum = v0 + v1;
#pragma unroll
    for (int o = 16; o > 0; o >>= 1) sum += __shfl_xor_sync(0xffffffffu, sum, o);
    if ((tid & 31) == 0) ws[tid >> 5] = sum;
    __syncthreads();
    if (tid == 0) {
        float t = 0.f;
#pragma unroll
        for (int i = 0; i < 8; i++) t += ws[i];
        bc[0] = t * (1.f / DIM);
    }
    __syncthreads();
    float mu = bc[0];

    float d0 = v0 - mu, d1 = v1 - mu;
    float q = d0 * d0 + d1 * d1;
#pragma unroll
    for (int o = 16; o > 0; o >>= 1) q += __shfl_xor_sync(0xffffffffu, q, o);
    if ((tid & 31) == 0) ws[tid >> 5] = q;
    __syncthreads();
    if (tid == 0) {
        float t = 0.f;
#pragma unroll
        for (int i = 0; i < 8; i++) t += ws[i];
        bc[1] = rsqrtf(t * (1.f / DIM) + 1e-5f);
    }
    __syncthreads();
    float rstd = bc[1];

    y[tid] = d0 * rstd * g[tid] + b[tid];
    y[tid + 256] = d1 * rstd * g[tid + 256] + b[tid + 256];
}

// ---------------------------------------------------------------------------
// Pooling
// ---------------------------------------------------------------------------
__global__ void pool_init(float* s, float* m, int n)
{
    int i = blockIdx.x * blockDim.x + threadIdx.x;
    if (i < n) { s[i] = 0.f; m[i] = -INFINITY; }
}

__device__ __forceinline__ void atomicMaxF(float* addr, float val)
{
    int old = __float_as_int(*addr);
    while (__int_as_float(old) < val) {
        int assumed = old;
        old = atomicCAS((int*)addr, assumed, __float_as_int(val));
        if (old == assumed) break;
    }
}

// grid (16, 3 slots, 4 row-chunks); slot g <- streams {g, g+3, g+6}
__global__ void __launch_bounds__(256) pool_b(
    const float* __restrict__ Qb, float* __restrict__ sum,
    float* __restrict__ mx, int layer)
{
    int idx = blockIdx.x * 256 + threadIdx.x;   // (b,d)
    int bb = idx >> 9, d = idx & 511;
    int g = blockIdx.y;
    int r0 = blockIdx.z * 128;
    float s = 0.f, m = -INFINITY;
#pragma unroll
    for (int t = 0; t < 3; t++) {
        const float* p = Qb + (long)(g + t * 3) * USZ
                       + (long)bb * SEQ * DIM + (long)r0 * DIM + d;
        for (int r = 0; r < 128; r++) {
            float v = p[(long)r * DIM];
            s += v;
            m = fmaxf(m, v);
        }
    }
    int k = g * 2 + layer;
    atomicAdd(&sum[k * 4096 + idx], s);
    atomicMaxF(&mx[k * 4096 + idx], m);
}

// ---------------------------------------------------------------------------
// Classifier
// ---------------------------------------------------------------------------
__global__ void __launch_bounds__(256) clf_kernel(
    const float* __restrict__ sum, const float* __restrict__ mx,
    const float* __restrict__ W, float* __restrict__ out)
{
    int bb = blockIdx.x / 9, cls = blockIdx.x % 9;
    int tid = threadIdx.x;
    float acc = 0.f;
    for (int j = tid; j < 3072; j += 256) {
        int k = j >> 9, d = j & 511;
        float sm = sum[k * 4096 + bb * 512 + d] * (1.f / 1536.f);
        float mv = mx[k * 4096 + bb * 512 + d];
        acc += sm * W[(long)j * 9 + cls] + mv * W[(long)(3072 + j) * 9 + cls];
    }
    __shared__ float red[256];
    red[tid] = acc;
    __syncthreads();
    for (int s = 128; s > 0; s >>= 1) {
        if (tid < s) red[tid] += red[tid + s];
        __syncthreads();
    }
    if (tid == 0) out[bb * 9 + cls] = red[0];
}

// ---------------------------------------------------------------------------
// Host orchestration (single stream — stream/event creation is forbidden
// inside kernel_launch: it allocates device memory and trips _HX_ENFORCE)
// ---------------------------------------------------------------------------
extern "C" void kernel_launch(void* const* d_in, const int* in_sizes, int n_in,
                              void* d_out, int out_size)
{
    const float* l      = (const float*)d_in[0];
    const float* v      = (const float*)d_in[1];
    const float* a      = (const float*)d_in[2];
    const float* l_mask = (const float*)d_in[3];
    const float* v_mask = (const float*)d_in[4];
    const float* a_mask = (const float*)d_in[5];
    const float* wl     = (const float*)d_in[6];
    const float* wv     = (const float*)d_in[7];
    const float* wa     = (const float*)d_in[8];
    const float* n1_g   = (const float*)d_in[9];
    const float* n1_b   = (const float*)d_in[10];
    const float* proj_w = (const float*)d_in[11];
    const float* minus_w= (const float*)d_in[12];
    const float* n2_g   = (const float*)d_in[13];
    const float* n2_b   = (const float*)d_in[14];
    const float* cvec   = (const float*)d_in[15];
    const float* clf_w  = (const float*)d_in[16];
    float* out          = (float*)d_out;

    float *pU, *pqA, *pqB, *pctx, *ptmp, *pW, *psum, *pmax;
    cudaGetSymbolAddress((void**)&pU, g_U);
    cudaGetSymbolAddress((void**)&pqA, g_qA);
    cudaGetSymbolAddress((void**)&pqB, g_qB);
    cudaGetSymbolAddress((void**)&pctx, g_ctx);
    cudaGetSymbolAddress((void**)&ptmp, g_tmp);
    cudaGetSymbolAddress((void**)&pW, g_W);
    cudaGetSymbolAddress((void**)&psum, g_sum);
    cudaGetSymbolAddress((void**)&pmax, g_max);

    const int SMEM_ATTN = (512 * 68 + 32 * 68 + 32 * 516 + 256 + 64) * 4;
    cudaFuncSetAttribute(attn_fused<0>,
        cudaFuncAttributeMaxDynamicSharedMemorySize, SMEM_ATTN);
    cudaFuncSetAttribute(attn_fused<1>,
        cudaFuncAttributeMaxDynamicSharedMemorySize, SMEM_ATTN);

    pool_init<<<96, 256>>>(psum, pmax, 6 * BATCH * DIM);

    // W[i] = proj_w[i] @ minus_w[i][512:1024]  (batched over 18 blocks)
    tc_plain<<<dim3(8, 4, 18), 256>>>(
        proj_w, minus_w + (long)DIM * DIM, pW, DIM, DIM, DIM, DIM,
        (long)DIM * DIM, (long)2 * DIM * DIM, (long)DIM * DIM);

    // --- Unify + LN ---
    tc_plain<<<dim3(8, 32, 1), 256>>>(l, wl, ptmp, 768, 768, DIM, DIM, 0, 0, 0);
    ln_all<<<4096, 256>>>(ptmp, pU + 0 * USZ, n1_g, n1_b, 0);
    tc_plain<<<dim3(8, 32, 1), 256>>>(v, wv, ptmp, 640, 640, DIM, DIM, 0, 0, 0);
    ln_all<<<4096, 256>>>(ptmp, pU + 1 * USZ, n1_g, n1_b, 0);
    gen_gemm<<<dim3(8, 32), 256>>>(a, wa, ptmp, 4096, DIM, 205, 205, DIM, DIM);
    ln_all<<<4096, 256>>>(ptmp, pU + 2 * USZ, n1_g, n1_b, 0);

    // --- layer 0 (all 9 streams batched) ---
    attn_fused<0><<<576, 256, SMEM_ATTN>>>(
        pU, nullptr, pctx, l_mask, v_mask, a_mask, cvec);
    minus_b<0><<<dim3(8, 32, 9), 256>>>(pU, nullptr, pctx, minus_w, pW, ptmp);
    ln_all<<<9 * 4096, 256>>>(ptmp, pqA, n2_g, n2_b, 2 * DIM);
    pool_b<<<dim3(16, 3, 4), 256>>>(pqA, psum, pmax, 0);

    // --- layer 1 ---
    attn_fused<1><<<576, 256, SMEM_ATTN>>>(
        pU, pqA, pctx, l_mask, v_mask, a_mask, cvec);
    minus_b<1><<<dim3(8, 32, 9), 256>>>(pU, pqA, pctx, minus_w, pW, ptmp);
    ln_all<<<9 * 4096, 256>>>(ptmp, pqB, n2_g + DIM, n2_b + DIM, 2 * DIM);
    pool_b<<<dim3(16, 3, 4), 256>>>(pqB, psum, pmax, 1);

    clf_kernel<<<BATCH * 9, 256>>>(psum, pmax, clf_w, out);
}